// round 14
// baseline (speedup 1.0000x reference)
#include <cuda_runtime.h>
#include <math.h>

#define H   128
#define ED  64
#define MAXN 100000
#define MAXE 500000

// ---------------- scratch (device globals; no allocations allowed) ----------------
__device__ float    g_h[(size_t)MAXN * H];      // LN1 output; later reused to park out1
__device__ float    g_msg[(size_t)MAXE * H];    // gated messages
__device__ float    g_score[MAXE];              // attention scores
__device__ float    g_exp[MAXE];                // exp(score - max)
__device__ unsigned g_maxkey[MAXN];             // ordered-uint segment max
__device__ float    g_denom[MAXN];              // segment sum of exp
__device__ float    g_agg[(size_t)MAXN * H];    // aggregated messages
// node-level precomputed first-layer partials (no bias)
__device__ float    g_Pgd[(size_t)MAXN * H];    // h @ Wg1[0:128]    (dst part, gate)
__device__ float    g_Pgs[(size_t)MAXN * H];    // h @ Wg1[128:256]  (src part, gate)
__device__ float    g_Pad[(size_t)MAXN * H];    // h @ Wa1[0:128]    (dst part, attn)
__device__ float    g_Pas[(size_t)MAXN * H];    // h @ Wa1[128:256]  (src part, attn)
__device__ float    g_Pms[(size_t)MAXN * H];    // h @ Wm1[0:128]    (src part, msg)

// ---------------- helpers ----------------
__device__ __forceinline__ float gelu_exact(float v) {
    return 0.5f * v * (1.0f + erff(v * 0.70710678118654752440f));
}

__device__ __forceinline__ void cp16(float* dst, const float* src) {
    unsigned s = (unsigned)__cvta_generic_to_shared(dst);
    asm volatile("cp.async.cg.shared.global [%0], [%1], 16;" :: "r"(s), "l"(src) : "memory");
}
#define CP_COMMIT() asm volatile("cp.async.commit_group;" ::: "memory")
#define CP_WAIT0()  asm volatile("cp.async.wait_group 0;" ::: "memory")

// ---------------- templated tiled GEMM (A in smem) with cp.async weights ----------
// C[64 rows][128 cols] += A[64][K] * W[K][128]; 256 threads = 8 warps.
// Warp w: rows w*8..w*8+7. Lane l: cols l*4..l*4+3.
template<int K, int LDA, int LDW>
__device__ __forceinline__ void gemm_acc_t(
    const float* __restrict__ As,
    const float* __restrict__ Wg, int woff,
    float* __restrict__ Wts, float acc[8][4])
{
    constexpr int NT = K / 32;
    const int tx  = threadIdx.x;
    const int wid = tx >> 5;
    const int c0  = (tx & 31) * 4;
    const float* abase = As + (wid * 8) * LDA;
    const float* wptr  = Wg + (size_t)wid * LDW + woff + c0;
    float* s0 = Wts + wid * 128 + c0;

#pragma unroll
    for (int i = 0; i < 4; ++i)
        cp16(s0 + i * 8 * 128, wptr + (size_t)(i * 8) * LDW);
    CP_COMMIT();
    CP_WAIT0();
    __syncthreads();

    int cur = 0;
#pragma unroll 1
    for (int t = 0; t < NT; ++t) {
        if (t + 1 < NT) {
            float* sn = s0 + (cur ? 0 : 4096);
            const float* wn = wptr + (size_t)((t + 1) * 32) * LDW;
#pragma unroll
            for (int i = 0; i < 4; ++i)
                cp16(sn + i * 8 * 128, wn + (size_t)(i * 8) * LDW);
            CP_COMMIT();
        }
        const float* wb = Wts + (cur ? 4096 : 0);
        const float* ab = abase + t * 32;
#pragma unroll
        for (int kk4 = 0; kk4 < 32; kk4 += 4) {
            float4 b0 = *(const float4*)(wb + (kk4 + 0) * 128 + c0);
            float4 b1 = *(const float4*)(wb + (kk4 + 1) * 128 + c0);
            float4 b2 = *(const float4*)(wb + (kk4 + 2) * 128 + c0);
            float4 b3 = *(const float4*)(wb + (kk4 + 3) * 128 + c0);
#pragma unroll
            for (int er = 0; er < 8; ++er) {
                float4 a = *(const float4*)(ab + er * LDA + kk4);
                acc[er][0] = fmaf(a.x, b0.x, acc[er][0]);
                acc[er][1] = fmaf(a.x, b0.y, acc[er][1]);
                acc[er][2] = fmaf(a.x, b0.z, acc[er][2]);
                acc[er][3] = fmaf(a.x, b0.w, acc[er][3]);
                acc[er][0] = fmaf(a.y, b1.x, acc[er][0]);
                acc[er][1] = fmaf(a.y, b1.y, acc[er][1]);
                acc[er][2] = fmaf(a.y, b1.z, acc[er][2]);
                acc[er][3] = fmaf(a.y, b1.w, acc[er][3]);
                acc[er][0] = fmaf(a.z, b2.x, acc[er][0]);
                acc[er][1] = fmaf(a.z, b2.y, acc[er][1]);
                acc[er][2] = fmaf(a.z, b2.z, acc[er][2]);
                acc[er][3] = fmaf(a.z, b2.w, acc[er][3]);
                acc[er][0] = fmaf(a.w, b3.x, acc[er][0]);
                acc[er][1] = fmaf(a.w, b3.y, acc[er][1]);
                acc[er][2] = fmaf(a.w, b3.z, acc[er][2]);
                acc[er][3] = fmaf(a.w, b3.w, acc[er][3]);
            }
        }
        if (t + 1 < NT) {
            CP_WAIT0();
            __syncthreads();
            cur ^= 1;
        }
    }
    __syncthreads();   // protect Wts and As for the caller's next phase
}

// ---------------- GEMM variant: A rows read directly from GLOBAL (uniform LDG) ----
// arow[er] = pointer to row (warp-uniform). K<=64 fits one emb row.
// No trailing sync: Wt reuse is ordered by the NEXT gemm's prologue barrier.
template<int K>
__device__ __forceinline__ void gemm_accg(
    const float* arow0, const float* arow1, const float* arow2, const float* arow3,
    const float* arow4, const float* arow5, const float* arow6, const float* arow7,
    const float* __restrict__ Wg, float* __restrict__ Wts, float acc[8][4])
{
    constexpr int NT = K / 32;
    const int tx  = threadIdx.x;
    const int wid = tx >> 5;
    const int c0  = (tx & 31) * 4;
    const float* wptr = Wg + wid * 128 + c0;
    float* s0 = Wts + wid * 128 + c0;
    const float* ar[8] = {arow0, arow1, arow2, arow3, arow4, arow5, arow6, arow7};

#pragma unroll
    for (int i = 0; i < 4; ++i)
        cp16(s0 + i * 8 * 128, wptr + i * 8 * 128);
    CP_COMMIT();
    CP_WAIT0();
    __syncthreads();

    int cur = 0;
#pragma unroll 1
    for (int t = 0; t < NT; ++t) {
        if (t + 1 < NT) {
            float* sn = s0 + (cur ? 0 : 4096);
            const float* wn = wptr + (t + 1) * 32 * 128;
#pragma unroll
            for (int i = 0; i < 4; ++i)
                cp16(sn + i * 8 * 128, wn + i * 8 * 128);
            CP_COMMIT();
        }
        const float* wb = Wts + (cur ? 4096 : 0);
#pragma unroll
        for (int kk4 = 0; kk4 < 32; kk4 += 4) {
            float4 b0 = *(const float4*)(wb + (kk4 + 0) * 128 + c0);
            float4 b1 = *(const float4*)(wb + (kk4 + 1) * 128 + c0);
            float4 b2 = *(const float4*)(wb + (kk4 + 2) * 128 + c0);
            float4 b3 = *(const float4*)(wb + (kk4 + 3) * 128 + c0);
#pragma unroll
            for (int er = 0; er < 8; ++er) {
                float4 a = *(const float4*)(ar[er] + t * 32 + kk4);  // uniform LDG.128
                acc[er][0] = fmaf(a.x, b0.x, acc[er][0]);
                acc[er][1] = fmaf(a.x, b0.y, acc[er][1]);
                acc[er][2] = fmaf(a.x, b0.z, acc[er][2]);
                acc[er][3] = fmaf(a.x, b0.w, acc[er][3]);
                acc[er][0] = fmaf(a.y, b1.x, acc[er][0]);
                acc[er][1] = fmaf(a.y, b1.y, acc[er][1]);
                acc[er][2] = fmaf(a.y, b1.z, acc[er][2]);
                acc[er][3] = fmaf(a.y, b1.w, acc[er][3]);
                acc[er][0] = fmaf(a.z, b2.x, acc[er][0]);
                acc[er][1] = fmaf(a.z, b2.y, acc[er][1]);
                acc[er][2] = fmaf(a.z, b2.z, acc[er][2]);
                acc[er][3] = fmaf(a.z, b2.w, acc[er][3]);
                acc[er][0] = fmaf(a.w, b3.x, acc[er][0]);
                acc[er][1] = fmaf(a.w, b3.y, acc[er][1]);
                acc[er][2] = fmaf(a.w, b3.z, acc[er][2]);
                acc[er][3] = fmaf(a.w, b3.w, acc[er][3]);
            }
        }
        if (t + 1 < NT) {
            CP_WAIT0();
            __syncthreads();
            cur ^= 1;
        }
    }
}

// b4 must already point at this thread's 4 columns (base + c0)
__device__ __forceinline__ void init_acc_bias(float acc[8][4], const float* __restrict__ b4) {
    float4 bv = *(const float4*)b4;
#pragma unroll
    for (int er = 0; er < 8; ++er) {
        acc[er][0] = bv.x; acc[er][1] = bv.y; acc[er][2] = bv.z; acc[er][3] = bv.w;
    }
}

// acc = Pd[dst] + Ps[src] + bias (indices read from smem at call site)
__device__ __forceinline__ void load_acc_pp(
    float acc[8][4], const float* __restrict__ Pd, const float* __restrict__ Ps,
    const int* dsts, const int* srcs, const float* __restrict__ b, int c0)
{
    float4 bv = *(const float4*)(b + c0);
#pragma unroll
    for (int er = 0; er < 8; ++er) {
        float4 d0 = *(const float4*)(Pd + (size_t)dsts[er] * H + c0);
        float4 s0 = *(const float4*)(Ps + (size_t)srcs[er] * H + c0);
        acc[er][0] = d0.x + s0.x + bv.x;
        acc[er][1] = d0.y + s0.y + bv.y;
        acc[er][2] = d0.z + s0.z + bv.z;
        acc[er][3] = d0.w + s0.w + bv.w;
    }
}

__device__ __forceinline__ void load_acc_p(
    float acc[8][4], const float* __restrict__ Ps,
    const int* srcs, const float* __restrict__ b, int c0)
{
    float4 bv = *(const float4*)(b + c0);
#pragma unroll
    for (int er = 0; er < 8; ++er) {
        float4 s0 = *(const float4*)(Ps + (size_t)srcs[er] * H + c0);
        acc[er][0] = s0.x + bv.x;
        acc[er][1] = s0.y + bv.y;
        acc[er][2] = s0.z + bv.z;
        acc[er][3] = s0.w + bv.w;
    }
}

__device__ __forceinline__ void store_hidden_gelu(float acc[8][4], float* __restrict__ Hm,
                                                  int stride, int r0, int c0) {
#pragma unroll
    for (int er = 0; er < 8; ++er) {
        float4 v = make_float4(gelu_exact(acc[er][0]), gelu_exact(acc[er][1]),
                               gelu_exact(acc[er][2]), gelu_exact(acc[er][3]));
        *(float4*)(Hm + (r0 + er) * stride + c0) = v;
    }
}

// ---------------- K1: LN1 fused + node-level precompute of first-layer partials ----
__global__ __launch_bounds__(256, 2) void pre_kernel(
    const float* __restrict__ x,
    const float* __restrict__ ln1g, const float* __restrict__ ln1b,
    const float* __restrict__ Wg1, const float* __restrict__ Wa1,
    const float* __restrict__ Wm1, int N)
{
    extern __shared__ float sm[];
    float* At = sm;                 // [64][132]
    float* Wt = At + 64 * 132;      // 2 x [32][128]
    float* mu = Wt + 2 * 32 * 128;  // [64]
    float* rs = mu + 64;            // [64]

    int tx = threadIdx.x;
    int n_base = blockIdx.x * 64;
    { // gather x tile
        int le = tx >> 2, q = tx & 3;
        int n = n_base + le;
        bool valid = n < N;
        const float4* xr = (const float4*)(x + (size_t)(valid ? n : 0) * H);
        float* ar = At + le * 132;
        float4 z = make_float4(0.f, 0.f, 0.f, 0.f);
#pragma unroll
        for (int jj = 0; jj < 8; ++jj) { int j = q + jj * 4; *(float4*)(ar + j * 4) = valid ? xr[j] : z; }
    }
    __syncthreads();

    { // LN1 stats: 4 threads per row
        int row = tx >> 2, q = tx & 3;
        const float* xr = At + row * 132 + q * 32;
        float s = 0.f, s2 = 0.f;
#pragma unroll 8
        for (int c = 0; c < 32; ++c) { float v = xr[c]; s += v; s2 = fmaf(v, v, s2); }
        s  += __shfl_xor_sync(0xffffffffu, s, 1);
        s  += __shfl_xor_sync(0xffffffffu, s, 2);
        s2 += __shfl_xor_sync(0xffffffffu, s2, 1);
        s2 += __shfl_xor_sync(0xffffffffu, s2, 2);
        if (q == 0) {
            float m = s * (1.0f / 128.0f);
            mu[row] = m;
            rs[row] = rsqrtf(fmaxf(s2 * (1.0f / 128.0f) - m * m, 0.0f) + 1e-5f);
        }
    }
    __syncthreads();

    { // normalize At in place + write g_h (coalesced float4)
#pragma unroll
        for (int i = 0; i < 8; ++i) {
            int f4 = tx + i * 256;
            int row = f4 >> 5;
            int c4 = (f4 & 31);
            float m = mu[row], r = rs[row];
            float4 v = *(const float4*)(At + row * 132 + c4 * 4);
            float4 g = ((const float4*)ln1g)[c4];
            float4 b = ((const float4*)ln1b)[c4];
            float4 nv = make_float4((v.x - m) * r * g.x + b.x, (v.y - m) * r * g.y + b.y,
                                    (v.z - m) * r * g.z + b.z, (v.w - m) * r * g.w + b.w);
            *(float4*)(At + row * 132 + c4 * 4) = nv;
            int n = n_base + row;
            if (n < N) ((float4*)(g_h + (size_t)n * H))[c4] = nv;
        }
    }

    int r0 = (tx >> 5) * 8;
    int c0 = (tx & 31) * 4;
    const float* Ws[5] = {Wg1, Wg1 + 128 * 128, Wa1, Wa1 + 128 * 128, Wm1};
    float* Os[5];
    Os[0] = g_Pgd; Os[1] = g_Pgs; Os[2] = g_Pad; Os[3] = g_Pas; Os[4] = g_Pms;

#pragma unroll 1
    for (int p = 0; p < 5; ++p) {
        float acc[8][4];
#pragma unroll
        for (int er = 0; er < 8; ++er)
#pragma unroll
            for (int cj = 0; cj < 4; ++cj) acc[er][cj] = 0.0f;
        gemm_acc_t<128, 132, 128>(At, Ws[p], 0, Wt, acc);
#pragma unroll
        for (int er = 0; er < 8; ++er) {
            int n = n_base + r0 + er;
            if (n < N) {
                *(float4*)(Os[p] + (size_t)n * H + c0) =
                    make_float4(acc[er][0], acc[er][1], acc[er][2], acc[er][3]);
            }
        }
    }
}

// ---------------- init: zero agg / denom / maxkey ----------------
__global__ __launch_bounds__(256) void init_kernel(int N)
{
    int i = blockIdx.x * 256 + threadIdx.x;
    if (i < N * H) g_agg[i] = 0.0f;
    if (i < N) { g_maxkey[i] = 0u; g_denom[i] = 0.0f; }
}

// ---------------- K2: per-edge MLPs (emb parts + second layers only) ----------------
__global__ __launch_bounds__(256, 3) void edge_kernel(
    const int* __restrict__ esrc, const int* __restrict__ edst,
    const float* __restrict__ emb,
    const float* __restrict__ Wm1, const float* __restrict__ bm1,
    const float* __restrict__ Wm2, const float* __restrict__ bm2,
    const float* __restrict__ Wa1, const float* __restrict__ ba1,
    const float* __restrict__ Wa2, const float* __restrict__ ba2,
    const float* __restrict__ Wg1, const float* __restrict__ bg1,
    const float* __restrict__ Wg2, const float* __restrict__ bg2,
    int E)
{
    extern __shared__ float sm[];
    float* Hm    = sm;                 // [64][132] hidden buffer
    float* Wt    = Hm + 64 * 132;      // 2 x [32][128] weight tiles
    float* gateS = Wt + 2 * 32 * 128;  // [64]
    int*   sidx  = (int*)(gateS + 64); // [64]
    int*   didx  = sidx + 64;          // [64]

    int tx = threadIdx.x;
    int e_base = blockIdx.x * 64;

    if (tx < 64) {
        int e = e_base + tx;
        sidx[tx] = (e < E) ? esrc[e] : 0;
        didx[tx] = (e < E) ? edst[e] : 0;
    }
    __syncthreads();

    int r0 = (tx >> 5) * 8;
    int c0 = (tx & 31) * 4;
    float acc[8][4];

    // warp-uniform emb row pointers (clamped for tail block)
#define AROW(er) (emb + (size_t)(((e_base + r0 + (er)) < E) ? (e_base + r0 + (er)) : (E - 1)) * ED)
    const float* a0 = AROW(0); const float* a1 = AROW(1);
    const float* a2 = AROW(2); const float* a3 = AROW(3);
    const float* a4 = AROW(4); const float* a5 = AROW(5);
    const float* a6 = AROW(6); const float* a7 = AROW(7);
#undef AROW

    // ---- gate path: gelu(Pgd[dst]+Pgs[src]+emb@Wg1_emb+bg1) @ Wg2 -> sigmoid
    load_acc_pp(acc, g_Pgd, g_Pgs, didx + r0, sidx + r0, bg1, c0);
    gemm_accg<64>(a0, a1, a2, a3, a4, a5, a6, a7, Wg1 + (size_t)256 * 128, Wt, acc);
    store_hidden_gelu(acc, Hm, 132, r0, c0);
    __syncthreads();
    { // 4 threads per row: 32 MACs each + quad shfl reduce
        int row = tx >> 2, q = tx & 3;
        const float* hr = Hm + row * 132 + q * 32;
        const float* w  = Wg2 + q * 32;
        float s = 0.f;
#pragma unroll 8
        for (int c = 0; c < 32; ++c) s = fmaf(hr[c], w[c], s);
        s += __shfl_xor_sync(0xffffffffu, s, 1);
        s += __shfl_xor_sync(0xffffffffu, s, 2);
        if (q == 0) gateS[row] = 1.0f / (1.0f + expf(-(s + bg2[0])));
    }
    // next gemm's prologue sync separates dot reads of Hm from its overwrite

    // ---- attn path
    load_acc_pp(acc, g_Pad, g_Pas, didx + r0, sidx + r0, ba1, c0);
    gemm_accg<64>(a0, a1, a2, a3, a4, a5, a6, a7, Wa1 + (size_t)256 * 128, Wt, acc);
    store_hidden_gelu(acc, Hm, 132, r0, c0);
    __syncthreads();
    {
        int row = tx >> 2, q = tx & 3;
        const float* hr = Hm + row * 132 + q * 32;
        const float* w  = Wa2 + q * 32;
        float s = 0.f;
#pragma unroll 8
        for (int c = 0; c < 32; ++c) s = fmaf(hr[c], w[c], s);
        s += __shfl_xor_sync(0xffffffffu, s, 1);
        s += __shfl_xor_sync(0xffffffffu, s, 2);
        int e = e_base + row;
        if (q == 0 && e < E) g_score[e] = s + ba2[0];
    }

    // ---- msg path: gelu(Pms[src]+emb@Wm1_emb+bm1) @ Wm2 + bm2, then * gate
    load_acc_p(acc, g_Pms, sidx + r0, bm1, c0);
    gemm_accg<64>(a0, a1, a2, a3, a4, a5, a6, a7, Wm1 + (size_t)128 * 128, Wt, acc);
    store_hidden_gelu(acc, Hm, 132, r0, c0);
    init_acc_bias(acc, bm2 + c0);
    gemm_acc_t<128, 132, 128>(Hm, Wm2, 0, Wt, acc);
#pragma unroll
    for (int er = 0; er < 8; ++er) {
        int e = e_base + r0 + er;
        if (e < E) {
            float g = gateS[r0 + er];
            *(float4*)(g_msg + (size_t)e * H + c0) =
                make_float4(acc[er][0] * g, acc[er][1] * g, acc[er][2] * g, acc[er][3] * g);
        }
    }
}

// ---------------- K3: segment softmax ----------------
__global__ __launch_bounds__(256) void smax_kernel(const int* __restrict__ edst, int E)
{
    int e = blockIdx.x * 256 + threadIdx.x;
    if (e >= E) return;
    int i = __float_as_int(g_score[e]);
    unsigned key = (i >= 0) ? ((unsigned)i ^ 0x80000000u) : ~(unsigned)i;
    atomicMax(&g_maxkey[edst[e]], key);
}

__global__ __launch_bounds__(256) void exps_kernel(const int* __restrict__ edst, int E)
{
    int e = blockIdx.x * 256 + threadIdx.x;
    if (e >= E) return;
    int d = edst[e];
    unsigned k = g_maxkey[d];
    int bits = (k & 0x80000000u) ? (int)(k ^ 0x80000000u) : (int)~k;
    float m = __int_as_float(bits);
    float v = expf(g_score[e] - m);
    g_exp[e] = v;
    atomicAdd(&g_denom[d], v);
}

// ---------------- K4: edge_repr + scatter-add agg (vectorized red) ----------------
__global__ __launch_bounds__(256) void scatter_kernel(
    const int* __restrict__ edst, float* __restrict__ erep, int E)
{
    int idx = blockIdx.x * 256 + threadIdx.x;
    int e = idx >> 5;
    if (e >= E) return;
    int l4 = idx & 31;
    int d = edst[e];
    float w = g_exp[e] / fmaxf(g_denom[d], 1e-12f);
    float4 m = ((const float4*)(g_msg + (size_t)e * H))[l4];
    float4 r = make_float4(m.x * w, m.y * w, m.z * w, m.w * w);
    ((float4*)(erep + (size_t)e * H))[l4] = r;
    float* ag = g_agg + (size_t)d * H + (size_t)l4 * 4;
    asm volatile("red.global.add.v4.f32 [%0], {%1, %2, %3, %4};"
                 :: "l"(ag), "f"(r.x), "f"(r.y), "f"(r.z), "f"(r.w)
                 : "memory");
}

// ---------------- K5: node update + LN2 + FFN (2 blocks/SM) ----------------
__global__ __launch_bounds__(256, 2) void node_kernel(
    const float* __restrict__ x,
    const float* __restrict__ Wself, const float* __restrict__ bself,
    const float* __restrict__ Wagg, const float* __restrict__ bagg,
    const float* __restrict__ g2, const float* __restrict__ b2,
    const float* __restrict__ Wf1, const float* __restrict__ bf1,
    const float* __restrict__ Wf2, const float* __restrict__ bf2,
    float* __restrict__ out, int N)
{
    extern __shared__ float sm[];
    float* At = sm;                  // [64][132] A operand (h, then agg, then LN2(out1))
    float* Hc = At + 64 * 132;       // [64][132] FFN hidden chunk
    float* Wt = Hc + 64 * 132;       // 2 x [32][128]

    int tx = threadIdx.x;
    int n_base = blockIdx.x * 64;
    int r0 = (tx >> 5) * 8;
    int c0 = (tx & 31) * 4;
    float acc[8][4];

    { // gather h
        int le = tx >> 2, q = tx & 3;
        int n = n_base + le;
        bool valid = n < N;
        const float4* hr = (const float4*)(g_h + (size_t)(valid ? n : 0) * H);
        float* ar = At + le * 132;
        float4 z = make_float4(0.f, 0.f, 0.f, 0.f);
#pragma unroll
        for (int jj = 0; jj < 8; ++jj) { int j = q + jj * 4; *(float4*)(ar + j * 4) = valid ? hr[j] : z; }
    }

    { // acc = bself + bagg
        float4 a0 = *(const float4*)(bself + c0);
        float4 g0 = *(const float4*)(bagg + c0);
#pragma unroll
        for (int er = 0; er < 8; ++er) {
            acc[er][0] = a0.x + g0.x; acc[er][1] = a0.y + g0.y;
            acc[er][2] = a0.z + g0.z; acc[er][3] = a0.w + g0.w;
        }
    }
    gemm_acc_t<128, 132, 128>(At, Wself, 0, Wt, acc);

    { // overwrite At with agg (gemm's trailing sync makes this safe)
        int le = tx >> 2, q = tx & 3;
        int n = n_base + le;
        bool valid = n < N;
        const float4* gr = (const float4*)(g_agg + (size_t)(valid ? n : 0) * H);
        float* ar = At + le * 132;
        float4 z = make_float4(0.f, 0.f, 0.f, 0.f);
#pragma unroll
        for (int jj = 0; jj < 8; ++jj) { int j = q + jj * 4; *(float4*)(ar + j * 4) = valid ? gr[j] : z; }
    }
    gemm_acc_t<128, 132, 128>(At, Wagg, 0, Wt, acc);

    // out1 = x + update: park in g_h rows (ours alone), LN2 stats per warp-row,
    // normalized -> At.
    float4 gq = *(const float4*)(g2 + c0);
    float4 bq = *(const float4*)(b2 + c0);
#pragma unroll
    for (int er = 0; er < 8; ++er) {
        int n = n_base + r0 + er;
        float4 x0 = make_float4(0.f, 0.f, 0.f, 0.f);
        if (n < N) x0 = *(const float4*)(x + (size_t)n * H + c0);
        float o0 = acc[er][0] + x0.x, o1 = acc[er][1] + x0.y;
        float o2 = acc[er][2] + x0.z, o3 = acc[er][3] + x0.w;
        if (n < N)
            *(float4*)(g_h + (size_t)n * H + c0) = make_float4(o0, o1, o2, o3);
        float s  = o0 + o1 + o2 + o3;
        float s2 = o0 * o0 + o1 * o1 + o2 * o2 + o3 * o3;
#pragma unroll
        for (int o = 16; o; o >>= 1) {
            s  += __shfl_xor_sync(0xffffffffu, s,  o);
            s2 += __shfl_xor_sync(0xffffffffu, s2, o);
        }
        float m = s * (1.0f / 128.0f);
        float r = rsqrtf(fmaxf(s2 * (1.0f / 128.0f) - m * m, 0.0f) + 1e-5f);
        *(float4*)(At + (r0 + er) * 132 + c0) =
            make_float4((o0 - m) * r * gq.x + bq.x, (o1 - m) * r * gq.y + bq.y,
                        (o2 - m) * r * gq.z + bq.z, (o3 - m) * r * gq.w + bq.w);
    }

    // FFN chunked: gelu hidden chunk -> Hc, then FFN2 partial into persistent accB.
    float accB[8][4];
    {
        float4 bv = *(const float4*)(bf2 + c0);
#pragma unroll
        for (int er = 0; er < 8; ++er) {
            accB[er][0] = bv.x; accB[er][1] = bv.y; accB[er][2] = bv.z; accB[er][3] = bv.w;
        }
    }
#pragma unroll 1
    for (int chunk = 0; chunk < 2; ++chunk) {
        int coff = chunk * 128;
        init_acc_bias(acc, bf1 + coff + c0);
        gemm_acc_t<128, 132, 256>(At, Wf1, coff, Wt, acc);
        store_hidden_gelu(acc, Hc, 132, r0, c0);
        gemm_acc_t<128, 132, 128>(Hc, Wf2 + (size_t)coff * 128, 0, Wt, accB);
    }

    // final: out = out1(g_h) + accB
#pragma unroll
    for (int er = 0; er < 8; ++er) {
        int n = n_base + r0 + er;
        if (n < N) {
            float4 o = *(const float4*)(g_h + (size_t)n * H + c0);
            *(float4*)(out + (size_t)n * H + c0) =
                make_float4(o.x + accB[er][0], o.y + accB[er][1],
                            o.z + accB[er][2], o.w + accB[er][3]);
        }
    }
}

// ---------------- launch ----------------
extern "C" void kernel_launch(void* const* d_in, const int* in_sizes, int n_in,
                              void* d_out, int out_size)
{
    const float* x     = (const float*)d_in[0];
    const int*   esrc  = (const int*)d_in[1];
    const int*   edst  = (const int*)d_in[2];
    const float* emb   = (const float*)d_in[3];
    const float* ln1g  = (const float*)d_in[4];
    const float* ln1b  = (const float*)d_in[5];
    const float* ln2g  = (const float*)d_in[6];
    const float* ln2b  = (const float*)d_in[7];
    const float* Wself = (const float*)d_in[8];
    const float* bself = (const float*)d_in[9];
    const float* Wm1   = (const float*)d_in[10];
    const float* bm1   = (const float*)d_in[11];
    const float* Wm2   = (const float*)d_in[12];
    const float* bm2   = (const float*)d_in[13];
    const float* Wa1   = (const float*)d_in[14];
    const float* ba1   = (const float*)d_in[15];
    const float* Wa2   = (const float*)d_in[16];
    const float* ba2   = (const float*)d_in[17];
    const float* Wg1   = (const float*)d_in[18];
    const float* bg1   = (const float*)d_in[19];
    const float* Wg2   = (const float*)d_in[20];
    const float* bg2   = (const float*)d_in[21];
    const float* Wagg  = (const float*)d_in[22];
    const float* bagg  = (const float*)d_in[23];
    const float* Wf1   = (const float*)d_in[24];
    const float* bf1   = (const float*)d_in[25];
    const float* Wf2   = (const float*)d_in[26];
    const float* bf2   = (const float*)d_in[27];

    int N = in_sizes[0] / H;
    int E = in_sizes[1];

    float* out_nodes = (float*)d_out;
    float* out_edges = out_nodes + (size_t)N * H;

    const int PRE_SMEM  = (64 * 132 + 2 * 32 * 128 + 128) * 4;              // 67072
    const int EDGE_SMEM = (64 * 132 + 2 * 32 * 128 + 64 + 128) * 4;         // 67328
    const int NODE_SMEM = (64 * 132 * 2 + 2 * 32 * 128) * 4;                // 100352
    cudaFuncSetAttribute(pre_kernel,  cudaFuncAttributeMaxDynamicSharedMemorySize, PRE_SMEM);
    cudaFuncSetAttribute(edge_kernel, cudaFuncAttributeMaxDynamicSharedMemorySize, EDGE_SMEM);
    cudaFuncSetAttribute(node_kernel, cudaFuncAttributeMaxDynamicSharedMemorySize, NODE_SMEM);

    pre_kernel<<<(N + 63) / 64, 256, PRE_SMEM>>>(x, ln1g, ln1b, Wg1, Wa1, Wm1, N);
    init_kernel<<<(N * H + 255) / 256, 256>>>(N);
    edge_kernel<<<(E + 63) / 64, 256, EDGE_SMEM>>>(
        esrc, edst, emb, Wm1, bm1, Wm2, bm2, Wa1, ba1, Wa2, ba2,
        Wg1, bg1, Wg2, bg2, E);
    smax_kernel<<<(E + 255) / 256, 256>>>(edst, E);
    exps_kernel<<<(E + 255) / 256, 256>>>(edst, E);
    scatter_kernel<<<((size_t)E * 32 + 255) / 256, 256>>>(edst, out_edges, E);
    node_kernel<<<(N + 63) / 64, 256, NODE_SMEM>>>(
        x, Wself, bself, Wagg, bagg, ln2g, ln2b, Wf1, bf1, Wf2, bf2,
        out_nodes, N);
}

// round 15
// speedup vs baseline: 1.1803x; 1.1803x over previous
#include <cuda_runtime.h>
#include <math.h>

#define H   128
#define ED  64
#define MAXN 100000
#define MAXE 500000

// ---------------- scratch (device globals; no allocations allowed) ----------------
__device__ float    g_h[(size_t)MAXN * H];      // LN1 output; later reused to park out1
__device__ float    g_msg[(size_t)MAXE * H];    // gated messages
__device__ float    g_score[MAXE];              // attention scores
__device__ float    g_exp[MAXE];                // exp(score - max)
__device__ unsigned g_maxkey[MAXN];             // ordered-uint segment max
__device__ float    g_denom[MAXN];              // segment sum of exp
__device__ float    g_agg[(size_t)MAXN * H];    // aggregated messages
// node-level precomputed first-layer partials (no bias)
__device__ float    g_Pgd[(size_t)MAXN * H];    // h @ Wg1[0:128]    (dst part, gate)
__device__ float    g_Pgs[(size_t)MAXN * H];    // h @ Wg1[128:256]  (src part, gate)
__device__ float    g_Pad[(size_t)MAXN * H];    // h @ Wa1[0:128]    (dst part, attn)
__device__ float    g_Pas[(size_t)MAXN * H];    // h @ Wa1[128:256]  (src part, attn)
__device__ float    g_Pms[(size_t)MAXN * H];    // h @ Wm1[0:128]    (src part, msg)

// ---------------- helpers ----------------
__device__ __forceinline__ float gelu_exact(float v) {
    return 0.5f * v * (1.0f + erff(v * 0.70710678118654752440f));
}

__device__ __forceinline__ void cp16(float* dst, const float* src) {
    unsigned s = (unsigned)__cvta_generic_to_shared(dst);
    asm volatile("cp.async.cg.shared.global [%0], [%1], 16;" :: "r"(s), "l"(src) : "memory");
}
#define CP_COMMIT() asm volatile("cp.async.commit_group;" ::: "memory")
#define CP_WAIT0()  asm volatile("cp.async.wait_group 0;" ::: "memory")

// ---------------- templated tiled GEMM (A in smem) with cp.async weights ----------
// C[64 rows][128 cols] += A[64][K] * W[K][128]; 256 threads = 8 warps.
// Warp w: rows w*8..w*8+7. Lane l: cols l*4..l*4+3.
template<int K, int LDA, int LDW>
__device__ __forceinline__ void gemm_acc_t(
    const float* __restrict__ As,
    const float* __restrict__ Wg, int woff,
    float* __restrict__ Wts, float acc[8][4])
{
    constexpr int NT = K / 32;
    const int tx  = threadIdx.x;
    const int wid = tx >> 5;
    const int c0  = (tx & 31) * 4;
    const float* abase = As + (wid * 8) * LDA;
    const float* wptr  = Wg + (size_t)wid * LDW + woff + c0;
    float* s0 = Wts + wid * 128 + c0;

#pragma unroll
    for (int i = 0; i < 4; ++i)
        cp16(s0 + i * 8 * 128, wptr + (size_t)(i * 8) * LDW);
    CP_COMMIT();
    CP_WAIT0();
    __syncthreads();

    int cur = 0;
#pragma unroll 1
    for (int t = 0; t < NT; ++t) {
        if (t + 1 < NT) {
            float* sn = s0 + (cur ? 0 : 4096);
            const float* wn = wptr + (size_t)((t + 1) * 32) * LDW;
#pragma unroll
            for (int i = 0; i < 4; ++i)
                cp16(sn + i * 8 * 128, wn + (size_t)(i * 8) * LDW);
            CP_COMMIT();
        }
        const float* wb = Wts + (cur ? 4096 : 0);
        const float* ab = abase + t * 32;
#pragma unroll
        for (int kk4 = 0; kk4 < 32; kk4 += 4) {
            float4 b0 = *(const float4*)(wb + (kk4 + 0) * 128 + c0);
            float4 b1 = *(const float4*)(wb + (kk4 + 1) * 128 + c0);
            float4 b2 = *(const float4*)(wb + (kk4 + 2) * 128 + c0);
            float4 b3 = *(const float4*)(wb + (kk4 + 3) * 128 + c0);
#pragma unroll
            for (int er = 0; er < 8; ++er) {
                float4 a = *(const float4*)(ab + er * LDA + kk4);
                acc[er][0] = fmaf(a.x, b0.x, acc[er][0]);
                acc[er][1] = fmaf(a.x, b0.y, acc[er][1]);
                acc[er][2] = fmaf(a.x, b0.z, acc[er][2]);
                acc[er][3] = fmaf(a.x, b0.w, acc[er][3]);
                acc[er][0] = fmaf(a.y, b1.x, acc[er][0]);
                acc[er][1] = fmaf(a.y, b1.y, acc[er][1]);
                acc[er][2] = fmaf(a.y, b1.z, acc[er][2]);
                acc[er][3] = fmaf(a.y, b1.w, acc[er][3]);
                acc[er][0] = fmaf(a.z, b2.x, acc[er][0]);
                acc[er][1] = fmaf(a.z, b2.y, acc[er][1]);
                acc[er][2] = fmaf(a.z, b2.z, acc[er][2]);
                acc[er][3] = fmaf(a.z, b2.w, acc[er][3]);
                acc[er][0] = fmaf(a.w, b3.x, acc[er][0]);
                acc[er][1] = fmaf(a.w, b3.y, acc[er][1]);
                acc[er][2] = fmaf(a.w, b3.z, acc[er][2]);
                acc[er][3] = fmaf(a.w, b3.w, acc[er][3]);
            }
        }
        if (t + 1 < NT) {
            CP_WAIT0();
            __syncthreads();
            cur ^= 1;
        }
    }
    __syncthreads();   // protect Wts and As for the caller's next phase
}

// ---------------- K=64 split gemm: prefetch (issue cp) + compute (pure FMA) ------
// Weights 64x128 fit the full 32KB Wt buffer; no mid-tile barrier needed.
__device__ __forceinline__ void prefetch64(const float* __restrict__ Wg,
                                           float* __restrict__ Wts)
{
    const int tx  = threadIdx.x;
    const int wid = tx >> 5;
    const int c0  = (tx & 31) * 4;
#pragma unroll
    for (int i = 0; i < 8; ++i)
        cp16(Wts + (wid + i * 8) * 128 + c0, Wg + (size_t)(wid + i * 8) * 128 + c0);
    CP_COMMIT();
}

// Caller must have done CP_WAIT0(); __syncthreads(); after prefetch64 before this.
// Ends with __syncthreads() so Wts may be re-prefetched immediately after.
template<int LDA>
__device__ __forceinline__ void compute64(
    const float* __restrict__ As, const float* __restrict__ Wts, float acc[8][4])
{
    const int tx  = threadIdx.x;
    const int wid = tx >> 5;
    const int c0  = (tx & 31) * 4;
    const float* abase = As + (wid * 8) * LDA;

#pragma unroll 1
    for (int t = 0; t < 2; ++t) {
        const float* wb = Wts + t * 32 * 128;
        const float* ab = abase + t * 32;
#pragma unroll
        for (int kk4 = 0; kk4 < 32; kk4 += 4) {
            float4 b0 = *(const float4*)(wb + (kk4 + 0) * 128 + c0);
            float4 b1 = *(const float4*)(wb + (kk4 + 1) * 128 + c0);
            float4 b2 = *(const float4*)(wb + (kk4 + 2) * 128 + c0);
            float4 b3 = *(const float4*)(wb + (kk4 + 3) * 128 + c0);
#pragma unroll
            for (int er = 0; er < 8; ++er) {
                float4 a = *(const float4*)(ab + er * LDA + kk4);
                acc[er][0] = fmaf(a.x, b0.x, acc[er][0]);
                acc[er][1] = fmaf(a.x, b0.y, acc[er][1]);
                acc[er][2] = fmaf(a.x, b0.z, acc[er][2]);
                acc[er][3] = fmaf(a.x, b0.w, acc[er][3]);
                acc[er][0] = fmaf(a.y, b1.x, acc[er][0]);
                acc[er][1] = fmaf(a.y, b1.y, acc[er][1]);
                acc[er][2] = fmaf(a.y, b1.z, acc[er][2]);
                acc[er][3] = fmaf(a.y, b1.w, acc[er][3]);
                acc[er][0] = fmaf(a.z, b2.x, acc[er][0]);
                acc[er][1] = fmaf(a.z, b2.y, acc[er][1]);
                acc[er][2] = fmaf(a.z, b2.z, acc[er][2]);
                acc[er][3] = fmaf(a.z, b2.w, acc[er][3]);
                acc[er][0] = fmaf(a.w, b3.x, acc[er][0]);
                acc[er][1] = fmaf(a.w, b3.y, acc[er][1]);
                acc[er][2] = fmaf(a.w, b3.z, acc[er][2]);
                acc[er][3] = fmaf(a.w, b3.w, acc[er][3]);
            }
        }
    }
    __syncthreads();   // all warps done reading Wts
}

// b4 must already point at this thread's 4 columns (base + c0)
__device__ __forceinline__ void init_acc_bias(float acc[8][4], const float* __restrict__ b4) {
    float4 bv = *(const float4*)b4;
#pragma unroll
    for (int er = 0; er < 8; ++er) {
        acc[er][0] = bv.x; acc[er][1] = bv.y; acc[er][2] = bv.z; acc[er][3] = bv.w;
    }
}

// acc = Pd[dst] + Ps[src] + bias  (per-thread float4 cells, from global/L2)
__device__ __forceinline__ void load_acc_pp(
    float acc[8][4], const float* __restrict__ Pd, const float* __restrict__ Ps,
    const int* dsts, const int* srcs, const float* __restrict__ b, int c0)
{
    float4 bv = *(const float4*)(b + c0);
#pragma unroll
    for (int er = 0; er < 8; ++er) {
        float4 d0 = *(const float4*)(Pd + (size_t)dsts[er] * H + c0);
        float4 s0 = *(const float4*)(Ps + (size_t)srcs[er] * H + c0);
        acc[er][0] = d0.x + s0.x + bv.x;
        acc[er][1] = d0.y + s0.y + bv.y;
        acc[er][2] = d0.z + s0.z + bv.z;
        acc[er][3] = d0.w + s0.w + bv.w;
    }
}

__device__ __forceinline__ void load_acc_p(
    float acc[8][4], const float* __restrict__ Ps,
    const int* srcs, const float* __restrict__ b, int c0)
{
    float4 bv = *(const float4*)(b + c0);
#pragma unroll
    for (int er = 0; er < 8; ++er) {
        float4 s0 = *(const float4*)(Ps + (size_t)srcs[er] * H + c0);
        acc[er][0] = s0.x + bv.x;
        acc[er][1] = s0.y + bv.y;
        acc[er][2] = s0.z + bv.z;
        acc[er][3] = s0.w + bv.w;
    }
}

__device__ __forceinline__ void store_hidden_gelu(float acc[8][4], float* __restrict__ Hm,
                                                  int stride, int r0, int c0) {
#pragma unroll
    for (int er = 0; er < 8; ++er) {
        float4 v = make_float4(gelu_exact(acc[er][0]), gelu_exact(acc[er][1]),
                               gelu_exact(acc[er][2]), gelu_exact(acc[er][3]));
        *(float4*)(Hm + (r0 + er) * stride + c0) = v;
    }
}

// ---------------- K1: LN1 fused + node-level precompute of first-layer partials ----
__global__ __launch_bounds__(256, 2) void pre_kernel(
    const float* __restrict__ x,
    const float* __restrict__ ln1g, const float* __restrict__ ln1b,
    const float* __restrict__ Wg1, const float* __restrict__ Wa1,
    const float* __restrict__ Wm1, int N)
{
    extern __shared__ float sm[];
    float* At = sm;                 // [64][132]
    float* Wt = At + 64 * 132;      // 2 x [32][128]
    float* mu = Wt + 2 * 32 * 128;  // [64]
    float* rs = mu + 64;            // [64]

    int tx = threadIdx.x;
    int n_base = blockIdx.x * 64;
    { // gather x tile
        int le = tx >> 2, q = tx & 3;
        int n = n_base + le;
        bool valid = n < N;
        const float4* xr = (const float4*)(x + (size_t)(valid ? n : 0) * H);
        float* ar = At + le * 132;
        float4 z = make_float4(0.f, 0.f, 0.f, 0.f);
#pragma unroll
        for (int jj = 0; jj < 8; ++jj) { int j = q + jj * 4; *(float4*)(ar + j * 4) = valid ? xr[j] : z; }
    }
    __syncthreads();

    { // LN1 stats: 4 threads per row
        int row = tx >> 2, q = tx & 3;
        const float* xr = At + row * 132 + q * 32;
        float s = 0.f, s2 = 0.f;
#pragma unroll 8
        for (int c = 0; c < 32; ++c) { float v = xr[c]; s += v; s2 = fmaf(v, v, s2); }
        s  += __shfl_xor_sync(0xffffffffu, s, 1);
        s  += __shfl_xor_sync(0xffffffffu, s, 2);
        s2 += __shfl_xor_sync(0xffffffffu, s2, 1);
        s2 += __shfl_xor_sync(0xffffffffu, s2, 2);
        if (q == 0) {
            float m = s * (1.0f / 128.0f);
            mu[row] = m;
            rs[row] = rsqrtf(fmaxf(s2 * (1.0f / 128.0f) - m * m, 0.0f) + 1e-5f);
        }
    }
    __syncthreads();

    { // normalize At in place + write g_h (coalesced float4)
#pragma unroll
        for (int i = 0; i < 8; ++i) {
            int f4 = tx + i * 256;
            int row = f4 >> 5;
            int c4 = (f4 & 31);
            float m = mu[row], r = rs[row];
            float4 v = *(const float4*)(At + row * 132 + c4 * 4);
            float4 g = ((const float4*)ln1g)[c4];
            float4 b = ((const float4*)ln1b)[c4];
            float4 nv = make_float4((v.x - m) * r * g.x + b.x, (v.y - m) * r * g.y + b.y,
                                    (v.z - m) * r * g.z + b.z, (v.w - m) * r * g.w + b.w);
            *(float4*)(At + row * 132 + c4 * 4) = nv;
            int n = n_base + row;
            if (n < N) ((float4*)(g_h + (size_t)n * H))[c4] = nv;
        }
    }

    int r0 = (tx >> 5) * 8;
    int c0 = (tx & 31) * 4;
    const float* Ws[5] = {Wg1, Wg1 + 128 * 128, Wa1, Wa1 + 128 * 128, Wm1};
    float* Os[5];
    Os[0] = g_Pgd; Os[1] = g_Pgs; Os[2] = g_Pad; Os[3] = g_Pas; Os[4] = g_Pms;

#pragma unroll 1
    for (int p = 0; p < 5; ++p) {
        float acc[8][4];
#pragma unroll
        for (int er = 0; er < 8; ++er)
#pragma unroll
            for (int cj = 0; cj < 4; ++cj) acc[er][cj] = 0.0f;
        gemm_acc_t<128, 132, 128>(At, Ws[p], 0, Wt, acc);
#pragma unroll
        for (int er = 0; er < 8; ++er) {
            int n = n_base + r0 + er;
            if (n < N) {
                *(float4*)(Os[p] + (size_t)n * H + c0) =
                    make_float4(acc[er][0], acc[er][1], acc[er][2], acc[er][3]);
            }
        }
    }
}

// ---------------- init: zero agg / denom / maxkey ----------------
__global__ __launch_bounds__(256) void init_kernel(int N)
{
    int i = blockIdx.x * 256 + threadIdx.x;
    if (i < N * H) g_agg[i] = 0.0f;
    if (i < N) { g_maxkey[i] = 0u; g_denom[i] = 0.0f; }
}

// ---------------- K2: per-edge MLPs (emb parts + second layers only) ----------------
__global__ __launch_bounds__(256, 2) void edge_kernel(
    const int* __restrict__ esrc, const int* __restrict__ edst,
    const float* __restrict__ emb,
    const float* __restrict__ Wm1, const float* __restrict__ bm1,
    const float* __restrict__ Wm2, const float* __restrict__ bm2,
    const float* __restrict__ Wa1, const float* __restrict__ ba1,
    const float* __restrict__ Wa2, const float* __restrict__ ba2,
    const float* __restrict__ Wg1, const float* __restrict__ bg1,
    const float* __restrict__ Wg2, const float* __restrict__ bg2,
    int E)
{
    extern __shared__ float sm[];
    float* Hm    = sm;                 // [64][132] hidden buffer
    float* Fe    = Hm + 64 * 132;      // [64][68]  edge_emb tile
    float* Wt    = Fe + 64 * 68;       // [64][128] weight buffer (one-shot K=64)
    float* gateS = Wt + 64 * 128;      // [64]
    int*   sidx  = (int*)(gateS + 64); // [64]
    int*   didx  = sidx + 64;          // [64]

    int tx = threadIdx.x;
    int e_base = blockIdx.x * 64;

    // prefetch gate weights NOW — overlaps with the Fe gather below
    prefetch64(Wg1 + (size_t)256 * 128, Wt);

    if (tx < 64) {
        int e = e_base + tx;
        sidx[tx] = (e < E) ? esrc[e] : 0;
        didx[tx] = (e < E) ? edst[e] : 0;
    }
    { // gather edge_emb: 4 threads per edge, 4 float4 each
        int le = tx >> 2, q = tx & 3;
        int e = e_base + le;
        bool valid = e < E;
        const float4* em4 = (const float4*)(emb + (size_t)e * ED);
        float4 z = make_float4(0.f, 0.f, 0.f, 0.f);
        float* fr = Fe + le * 68;
#pragma unroll
        for (int jj = 0; jj < 4; ++jj) { int j = q + jj * 4; *(float4*)(fr + j * 4) = valid ? em4[j] : z; }
    }
    CP_WAIT0();
    __syncthreads();           // Fe + gate weights + indices all visible

    int r0 = (tx >> 5) * 8;
    int c0 = (tx & 31) * 4;
    float acc[8][4];
    int srcs[8], dsts[8];
#pragma unroll
    for (int er = 0; er < 8; ++er) { srcs[er] = sidx[r0 + er]; dsts[er] = didx[r0 + er]; }

    // ---- gate path: gelu(Pgd[dst]+Pgs[src]+emb@Wg1_emb+bg1) @ Wg2 -> sigmoid
    load_acc_pp(acc, g_Pgd, g_Pgs, dsts, srcs, bg1, c0);
    compute64<68>(Fe, Wt, acc);            // trailing sync: Wt free for re-prefetch
    prefetch64(Wa1 + (size_t)256 * 128, Wt);   // attn weights fetch overlaps dot phase
    store_hidden_gelu(acc, Hm, 132, r0, c0);
    __syncthreads();                       // Hm visible for dot phase
    { // 4 threads per row: 32 MACs each + quad shfl reduce
        int row = tx >> 2, q = tx & 3;
        const float* hr = Hm + row * 132 + q * 32;
        const float* w  = Wg2 + q * 32;
        float s = 0.f;
#pragma unroll 8
        for (int c = 0; c < 32; ++c) s = fmaf(hr[c], w[c], s);
        s += __shfl_xor_sync(0xffffffffu, s, 1);
        s += __shfl_xor_sync(0xffffffffu, s, 2);
        if (q == 0) gateS[row] = 1.0f / (1.0f + expf(-(s + bg2[0])));
    }
    CP_WAIT0();
    __syncthreads();                       // attn weights visible; dot reads of Hm done

    // ---- attn path
    load_acc_pp(acc, g_Pad, g_Pas, dsts, srcs, ba1, c0);
    compute64<68>(Fe, Wt, acc);
    prefetch64(Wm1 + (size_t)128 * 128, Wt);   // msg weights fetch overlaps dot phase
    store_hidden_gelu(acc, Hm, 132, r0, c0);
    __syncthreads();
    {
        int row = tx >> 2, q = tx & 3;
        const float* hr = Hm + row * 132 + q * 32;
        const float* w  = Wa2 + q * 32;
        float s = 0.f;
#pragma unroll 8
        for (int c = 0; c < 32; ++c) s = fmaf(hr[c], w[c], s);
        s += __shfl_xor_sync(0xffffffffu, s, 1);
        s += __shfl_xor_sync(0xffffffffu, s, 2);
        int e = e_base + row;
        if (q == 0 && e < E) g_score[e] = s + ba2[0];
    }
    CP_WAIT0();
    __syncthreads();                       // msg weights visible

    // ---- msg path: gelu(Pms[src]+emb@Wm1_emb+bm1) @ Wm2 + bm2, then * gate
    load_acc_p(acc, g_Pms, srcs, bm1, c0);
    compute64<68>(Fe, Wt, acc);
    store_hidden_gelu(acc, Hm, 132, r0, c0);
    init_acc_bias(acc, bm2 + c0);
    gemm_acc_t<128, 132, 128>(Hm, Wm2, 0, Wt, acc);  // its prologue sync covers Hm
#pragma unroll
    for (int er = 0; er < 8; ++er) {
        int e = e_base + r0 + er;
        if (e < E) {
            float g = gateS[r0 + er];
            *(float4*)(g_msg + (size_t)e * H + c0) =
                make_float4(acc[er][0] * g, acc[er][1] * g, acc[er][2] * g, acc[er][3] * g);
        }
    }
}

// ---------------- K3: segment softmax ----------------
__global__ __launch_bounds__(256) void smax_kernel(const int* __restrict__ edst, int E)
{
    int e = blockIdx.x * 256 + threadIdx.x;
    if (e >= E) return;
    int i = __float_as_int(g_score[e]);
    unsigned key = (i >= 0) ? ((unsigned)i ^ 0x80000000u) : ~(unsigned)i;
    atomicMax(&g_maxkey[edst[e]], key);
}

__global__ __launch_bounds__(256) void exps_kernel(const int* __restrict__ edst, int E)
{
    int e = blockIdx.x * 256 + threadIdx.x;
    if (e >= E) return;
    int d = edst[e];
    unsigned k = g_maxkey[d];
    int bits = (k & 0x80000000u) ? (int)(k ^ 0x80000000u) : (int)~k;
    float m = __int_as_float(bits);
    float v = expf(g_score[e] - m);
    g_exp[e] = v;
    atomicAdd(&g_denom[d], v);
}

// ---------------- K4: edge_repr + scatter-add agg (vectorized red) ----------------
__global__ __launch_bounds__(256) void scatter_kernel(
    const int* __restrict__ edst, float* __restrict__ erep, int E)
{
    int idx = blockIdx.x * 256 + threadIdx.x;
    int e = idx >> 5;
    if (e >= E) return;
    int l4 = idx & 31;
    int d = edst[e];
    float w = g_exp[e] / fmaxf(g_denom[d], 1e-12f);
    float4 m = ((const float4*)(g_msg + (size_t)e * H))[l4];
    float4 r = make_float4(m.x * w, m.y * w, m.z * w, m.w * w);
    ((float4*)(erep + (size_t)e * H))[l4] = r;
    float* ag = g_agg + (size_t)d * H + (size_t)l4 * 4;
    asm volatile("red.global.add.v4.f32 [%0], {%1, %2, %3, %4};"
                 :: "l"(ag), "f"(r.x), "f"(r.y), "f"(r.z), "f"(r.w)
                 : "memory");
}

// ---------------- K5: node update + LN2 + FFN (2 blocks/SM) ----------------
__global__ __launch_bounds__(256, 2) void node_kernel(
    const float* __restrict__ x,
    const float* __restrict__ Wself, const float* __restrict__ bself,
    const float* __restrict__ Wagg, const float* __restrict__ bagg,
    const float* __restrict__ g2, const float* __restrict__ b2,
    const float* __restrict__ Wf1, const float* __restrict__ bf1,
    const float* __restrict__ Wf2, const float* __restrict__ bf2,
    float* __restrict__ out, int N)
{
    extern __shared__ float sm[];
    float* At = sm;                  // [64][132] A operand (h, then agg, then LN2(out1))
    float* Hc = At + 64 * 132;       // [64][132] FFN hidden chunk
    float* Wt = Hc + 64 * 132;       // 2 x [32][128]

    int tx = threadIdx.x;
    int n_base = blockIdx.x * 64;
    int r0 = (tx >> 5) * 8;
    int c0 = (tx & 31) * 4;
    float acc[8][4];

    { // gather h
        int le = tx >> 2, q = tx & 3;
        int n = n_base + le;
        bool valid = n < N;
        const float4* hr = (const float4*)(g_h + (size_t)(valid ? n : 0) * H);
        float* ar = At + le * 132;
        float4 z = make_float4(0.f, 0.f, 0.f, 0.f);
#pragma unroll
        for (int jj = 0; jj < 8; ++jj) { int j = q + jj * 4; *(float4*)(ar + j * 4) = valid ? hr[j] : z; }
    }

    { // acc = bself + bagg
        float4 a0 = *(const float4*)(bself + c0);
        float4 g0 = *(const float4*)(bagg + c0);
#pragma unroll
        for (int er = 0; er < 8; ++er) {
            acc[er][0] = a0.x + g0.x; acc[er][1] = a0.y + g0.y;
            acc[er][2] = a0.z + g0.z; acc[er][3] = a0.w + g0.w;
        }
    }
    gemm_acc_t<128, 132, 128>(At, Wself, 0, Wt, acc);

    { // overwrite At with agg (gemm's trailing sync makes this safe)
        int le = tx >> 2, q = tx & 3;
        int n = n_base + le;
        bool valid = n < N;
        const float4* gr = (const float4*)(g_agg + (size_t)(valid ? n : 0) * H);
        float* ar = At + le * 132;
        float4 z = make_float4(0.f, 0.f, 0.f, 0.f);
#pragma unroll
        for (int jj = 0; jj < 8; ++jj) { int j = q + jj * 4; *(float4*)(ar + j * 4) = valid ? gr[j] : z; }
    }
    gemm_acc_t<128, 132, 128>(At, Wagg, 0, Wt, acc);

    // out1 = x + update: park in g_h rows (ours alone), LN2 stats per warp-row,
    // normalized -> At.
    float4 gq = *(const float4*)(g2 + c0);
    float4 bq = *(const float4*)(b2 + c0);
#pragma unroll
    for (int er = 0; er < 8; ++er) {
        int n = n_base + r0 + er;
        float4 x0 = make_float4(0.f, 0.f, 0.f, 0.f);
        if (n < N) x0 = *(const float4*)(x + (size_t)n * H + c0);
        float o0 = acc[er][0] + x0.x, o1 = acc[er][1] + x0.y;
        float o2 = acc[er][2] + x0.z, o3 = acc[er][3] + x0.w;
        if (n < N)
            *(float4*)(g_h + (size_t)n * H + c0) = make_float4(o0, o1, o2, o3);
        float s  = o0 + o1 + o2 + o3;
        float s2 = o0 * o0 + o1 * o1 + o2 * o2 + o3 * o3;
#pragma unroll
        for (int o = 16; o; o >>= 1) {
            s  += __shfl_xor_sync(0xffffffffu, s,  o);
            s2 += __shfl_xor_sync(0xffffffffu, s2, o);
        }
        float m = s * (1.0f / 128.0f);
        float r = rsqrtf(fmaxf(s2 * (1.0f / 128.0f) - m * m, 0.0f) + 1e-5f);
        *(float4*)(At + (r0 + er) * 132 + c0) =
            make_float4((o0 - m) * r * gq.x + bq.x, (o1 - m) * r * gq.y + bq.y,
                        (o2 - m) * r * gq.z + bq.z, (o3 - m) * r * gq.w + bq.w);
    }

    // FFN chunked: gelu hidden chunk -> Hc, then FFN2 partial into persistent accB.
    float accB[8][4];
    {
        float4 bv = *(const float4*)(bf2 + c0);
#pragma unroll
        for (int er = 0; er < 8; ++er) {
            accB[er][0] = bv.x; accB[er][1] = bv.y; accB[er][2] = bv.z; accB[er][3] = bv.w;
        }
    }
#pragma unroll 1
    for (int chunk = 0; chunk < 2; ++chunk) {
        int coff = chunk * 128;
        init_acc_bias(acc, bf1 + coff + c0);
        gemm_acc_t<128, 132, 256>(At, Wf1, coff, Wt, acc);
        store_hidden_gelu(acc, Hc, 132, r0, c0);
        gemm_acc_t<128, 132, 128>(Hc, Wf2 + (size_t)coff * 128, 0, Wt, accB);
    }

    // final: out = out1(g_h) + accB
#pragma unroll
    for (int er = 0; er < 8; ++er) {
        int n = n_base + r0 + er;
        if (n < N) {
            float4 o = *(const float4*)(g_h + (size_t)n * H + c0);
            *(float4*)(out + (size_t)n * H + c0) =
                make_float4(o.x + accB[er][0], o.y + accB[er][1],
                            o.z + accB[er][2], o.w + accB[er][3]);
        }
    }
}

// ---------------- launch ----------------
extern "C" void kernel_launch(void* const* d_in, const int* in_sizes, int n_in,
                              void* d_out, int out_size)
{
    const float* x     = (const float*)d_in[0];
    const int*   esrc  = (const int*)d_in[1];
    const int*   edst  = (const int*)d_in[2];
    const float* emb   = (const float*)d_in[3];
    const float* ln1g  = (const float*)d_in[4];
    const float* ln1b  = (const float*)d_in[5];
    const float* ln2g  = (const float*)d_in[6];
    const float* ln2b  = (const float*)d_in[7];
    const float* Wself = (const float*)d_in[8];
    const float* bself = (const float*)d_in[9];
    const float* Wm1   = (const float*)d_in[10];
    const float* bm1   = (const float*)d_in[11];
    const float* Wm2   = (const float*)d_in[12];
    const float* bm2   = (const float*)d_in[13];
    const float* Wa1   = (const float*)d_in[14];
    const float* ba1   = (const float*)d_in[15];
    const float* Wa2   = (const float*)d_in[16];
    const float* ba2   = (const float*)d_in[17];
    const float* Wg1   = (const float*)d_in[18];
    const float* bg1   = (const float*)d_in[19];
    const float* Wg2   = (const float*)d_in[20];
    const float* bg2   = (const float*)d_in[21];
    const float* Wagg  = (const float*)d_in[22];
    const float* bagg  = (const float*)d_in[23];
    const float* Wf1   = (const float*)d_in[24];
    const float* bf1   = (const float*)d_in[25];
    const float* Wf2   = (const float*)d_in[26];
    const float* bf2   = (const float*)d_in[27];

    int N = in_sizes[0] / H;
    int E = in_sizes[1];

    float* out_nodes = (float*)d_out;
    float* out_edges = out_nodes + (size_t)N * H;

    const int PRE_SMEM  = (64 * 132 + 2 * 32 * 128 + 128) * 4;                    // 67072
    const int EDGE_SMEM = (64 * 132 + 64 * 68 + 64 * 128 + 64 + 128) * 4;         // 84736
    const int NODE_SMEM = (64 * 132 * 2 + 2 * 32 * 128) * 4;                      // 100352
    cudaFuncSetAttribute(pre_kernel,  cudaFuncAttributeMaxDynamicSharedMemorySize, PRE_SMEM);
    cudaFuncSetAttribute(edge_kernel, cudaFuncAttributeMaxDynamicSharedMemorySize, EDGE_SMEM);
    cudaFuncSetAttribute(node_kernel, cudaFuncAttributeMaxDynamicSharedMemorySize, NODE_SMEM);

    pre_kernel<<<(N + 63) / 64, 256, PRE_SMEM>>>(x, ln1g, ln1b, Wg1, Wa1, Wm1, N);
    init_kernel<<<(N * H + 255) / 256, 256>>>(N);
    edge_kernel<<<(E + 63) / 64, 256, EDGE_SMEM>>>(
        esrc, edst, emb, Wm1, bm1, Wm2, bm2, Wa1, ba1, Wa2, ba2,
        Wg1, bg1, Wg2, bg2, E);
    smax_kernel<<<(E + 255) / 256, 256>>>(edst, E);
    exps_kernel<<<(E + 255) / 256, 256>>>(edst, E);
    scatter_kernel<<<((size_t)E * 32 + 255) / 256, 256>>>(edst, out_edges, E);
    node_kernel<<<(N + 63) / 64, 256, NODE_SMEM>>>(
        x, Wself, bself, Wagg, bagg, ln2g, ln2b, Wf1, bf1, Wf2, bf2,
        out_nodes, N);
}

// round 16
// speedup vs baseline: 1.4508x; 1.2292x over previous
#include <cuda_runtime.h>
#include <math.h>

#define H   128
#define ED  64
#define MAXN 100000
#define MAXE 500000

// ---------------- scratch (device globals; no allocations allowed) ----------------
__device__ float    g_h[(size_t)MAXN * H];      // LN1 output; later reused to park out1
__device__ float    g_msg[(size_t)MAXE * H];    // gated messages
__device__ float    g_score[MAXE];              // attention scores
__device__ float    g_exp[MAXE];                // exp(score - max)
__device__ unsigned g_maxkey[MAXN];             // ordered-uint segment max
__device__ float    g_denom[MAXN];              // segment sum of exp
__device__ float    g_agg[(size_t)MAXN * H];    // aggregated messages
// node-level precomputed first-layer partials (no bias)
__device__ float    g_Pgd[(size_t)MAXN * H];
__device__ float    g_Pgs[(size_t)MAXN * H];
__device__ float    g_Pad[(size_t)MAXN * H];
__device__ float    g_Pas[(size_t)MAXN * H];
__device__ float    g_Pms[(size_t)MAXN * H];

// ---------------- helpers ----------------
__device__ __forceinline__ float gelu_exact(float v) {
    return 0.5f * v * (1.0f + erff(v * 0.70710678118654752440f));
}

__device__ __forceinline__ void cp16(float* dst, const float* src) {
    unsigned s = (unsigned)__cvta_generic_to_shared(dst);
    asm volatile("cp.async.cg.shared.global [%0], [%1], 16;" :: "r"(s), "l"(src) : "memory");
}
#define CP_COMMIT() asm volatile("cp.async.commit_group;" ::: "memory")
#define CP_WAIT0()  asm volatile("cp.async.wait_group 0;" ::: "memory")

// ================= tf32 MMA tiled GEMM =================
// C[64 rows][128 cols] += A[64][K] * W[K][128]; A in smem row-major (stride LDA).
// W streamed global->smem via cp.async, smem tile 32 x 128 at padded stride 136.
// 8 warps: warp w -> m0 = (w&3)*16, n0 = (w>>2)*64 (16x64 per warp, 8 n-tiles).
// Fragment layout (m16n8k8): lane g=lane>>2, t=lane&3.
//   A: a0=(m0+g, k+t) a1=(m0+g+8, k+t) a2=(m0+g, k+t+4) a3=(m0+g+8, k+t+4)
//   B: b0=(k+t, n8+g) b1=(k+t+4, n8+g)
//   C: c0=(m0+g, n8+2t) c1=(..+1) c2=(m0+g+8, n8+2t) c3=(..+1)
#define LDW 136

template<int K, int LDA, int LDWG>
__device__ __forceinline__ void gemm_mma_t(
    const float* __restrict__ As,
    const float* __restrict__ Wg, int woff,
    float* __restrict__ Wts, float acc[8][4])
{
    constexpr int NT = K / 32;
    const int tx   = threadIdx.x;
    const int wid  = tx >> 5;
    const int lane = tx & 31;
    const int g = lane >> 2, t = lane & 3;
    const int m0 = (wid & 3) * 16;
    const int n0 = (wid >> 3 << 6);           // (wid>>2)*64 but wid<8 => wid>>2 in {0,1}
    const int n0b = (wid >> 2) * 64;
    (void)n0;
    const float* wptr = Wg + (size_t)wid * LDWG + woff + lane * 4;
    float* s0 = Wts + wid * LDW + lane * 4;

#pragma unroll
    for (int i = 0; i < 4; ++i)
        cp16(s0 + i * 8 * LDW, wptr + (size_t)(i * 8) * LDWG);
    CP_COMMIT();
    CP_WAIT0();
    __syncthreads();

    int cur = 0;
#pragma unroll 1
    for (int tt = 0; tt < NT; ++tt) {
        if (tt + 1 < NT) {
            float* sn = s0 + (cur ? 0 : 32 * LDW);
            const float* wn = wptr + (size_t)((tt + 1) * 32) * LDWG;
#pragma unroll
            for (int i = 0; i < 4; ++i)
                cp16(sn + i * 8 * LDW, wn + (size_t)(i * 8) * LDWG);
            CP_COMMIT();
        }
        const float* wb = Wts + (cur ? 32 * LDW : 0);
        const float* ab = As + tt * 32;
#pragma unroll
        for (int k8 = 0; k8 < 32; k8 += 8) {
            unsigned a0 = __float_as_uint(ab[(m0 + g)     * LDA + k8 + t]);
            unsigned a1 = __float_as_uint(ab[(m0 + g + 8) * LDA + k8 + t]);
            unsigned a2 = __float_as_uint(ab[(m0 + g)     * LDA + k8 + t + 4]);
            unsigned a3 = __float_as_uint(ab[(m0 + g + 8) * LDA + k8 + t + 4]);
#pragma unroll
            for (int nt = 0; nt < 8; ++nt) {
                int n8 = n0b + nt * 8;
                unsigned b0 = __float_as_uint(wb[(k8 + t)     * LDW + n8 + g]);
                unsigned b1 = __float_as_uint(wb[(k8 + t + 4) * LDW + n8 + g]);
                asm volatile(
                    "mma.sync.aligned.m16n8k8.row.col.f32.tf32.tf32.f32 "
                    "{%0,%1,%2,%3}, {%4,%5,%6,%7}, {%8,%9}, {%0,%1,%2,%3};"
                    : "+f"(acc[nt][0]), "+f"(acc[nt][1]),
                      "+f"(acc[nt][2]), "+f"(acc[nt][3])
                    : "r"(a0), "r"(a1), "r"(a2), "r"(a3), "r"(b0), "r"(b1));
            }
        }
        if (tt + 1 < NT) {
            CP_WAIT0();
            __syncthreads();
            cur ^= 1;
        }
    }
    __syncthreads();   // protect Wts and As for the caller's next phase
}

// init acc (mma layout) with bias at this thread's column pairs
__device__ __forceinline__ void mma_init_bias(float acc[8][4], const float* __restrict__ b,
                                              int n0b, int t) {
#pragma unroll
    for (int nt = 0; nt < 8; ++nt) {
        float2 bv = *(const float2*)(b + n0b + nt * 8 + 2 * t);
        acc[nt][0] = bv.x; acc[nt][1] = bv.y;
        acc[nt][2] = bv.x; acc[nt][3] = bv.y;
    }
}

// ---------------- fp32 FFMA GEMM (edge kernel keeps this proven path) ----------
template<int K, int LDA, int LDWG>
__device__ __forceinline__ void gemm_acc_t(
    const float* __restrict__ As,
    const float* __restrict__ Wg, int woff,
    float* __restrict__ Wts, float acc[8][4])
{
    constexpr int NT = K / 32;
    const int tx  = threadIdx.x;
    const int wid = tx >> 5;
    const int c0  = (tx & 31) * 4;
    const float* abase = As + (wid * 8) * LDA;
    const float* wptr  = Wg + (size_t)wid * LDWG + woff + c0;
    float* s0 = Wts + wid * 128 + c0;

#pragma unroll
    for (int i = 0; i < 4; ++i)
        cp16(s0 + i * 8 * 128, wptr + (size_t)(i * 8) * LDWG);
    CP_COMMIT();
    CP_WAIT0();
    __syncthreads();

    int cur = 0;
#pragma unroll 1
    for (int t = 0; t < NT; ++t) {
        if (t + 1 < NT) {
            float* sn = s0 + (cur ? 0 : 4096);
            const float* wn = wptr + (size_t)((t + 1) * 32) * LDWG;
#pragma unroll
            for (int i = 0; i < 4; ++i)
                cp16(sn + i * 8 * 128, wn + (size_t)(i * 8) * LDWG);
            CP_COMMIT();
        }
        const float* wb = Wts + (cur ? 4096 : 0);
        const float* ab = abase + t * 32;
#pragma unroll
        for (int kk4 = 0; kk4 < 32; kk4 += 4) {
            float4 b0 = *(const float4*)(wb + (kk4 + 0) * 128 + c0);
            float4 b1 = *(const float4*)(wb + (kk4 + 1) * 128 + c0);
            float4 b2 = *(const float4*)(wb + (kk4 + 2) * 128 + c0);
            float4 b3 = *(const float4*)(wb + (kk4 + 3) * 128 + c0);
#pragma unroll
            for (int er = 0; er < 8; ++er) {
                float4 a = *(const float4*)(ab + er * LDA + kk4);
                acc[er][0] = fmaf(a.x, b0.x, acc[er][0]);
                acc[er][1] = fmaf(a.x, b0.y, acc[er][1]);
                acc[er][2] = fmaf(a.x, b0.z, acc[er][2]);
                acc[er][3] = fmaf(a.x, b0.w, acc[er][3]);
                acc[er][0] = fmaf(a.y, b1.x, acc[er][0]);
                acc[er][1] = fmaf(a.y, b1.y, acc[er][1]);
                acc[er][2] = fmaf(a.y, b1.z, acc[er][2]);
                acc[er][3] = fmaf(a.y, b1.w, acc[er][3]);
                acc[er][0] = fmaf(a.z, b2.x, acc[er][0]);
                acc[er][1] = fmaf(a.z, b2.y, acc[er][1]);
                acc[er][2] = fmaf(a.z, b2.z, acc[er][2]);
                acc[er][3] = fmaf(a.z, b2.w, acc[er][3]);
                acc[er][0] = fmaf(a.w, b3.x, acc[er][0]);
                acc[er][1] = fmaf(a.w, b3.y, acc[er][1]);
                acc[er][2] = fmaf(a.w, b3.z, acc[er][2]);
                acc[er][3] = fmaf(a.w, b3.w, acc[er][3]);
            }
        }
        if (t + 1 < NT) {
            CP_WAIT0();
            __syncthreads();
            cur ^= 1;
        }
    }
    __syncthreads();
}

__device__ __forceinline__ void init_acc_bias(float acc[8][4], const float* __restrict__ b4) {
    float4 bv = *(const float4*)b4;
#pragma unroll
    for (int er = 0; er < 8; ++er) {
        acc[er][0] = bv.x; acc[er][1] = bv.y; acc[er][2] = bv.z; acc[er][3] = bv.w;
    }
}

__device__ __forceinline__ void load_acc_pp(
    float acc[8][4], const float* __restrict__ Pd, const float* __restrict__ Ps,
    const int* dsts, const int* srcs, const float* __restrict__ b, int c0)
{
    float4 bv = *(const float4*)(b + c0);
#pragma unroll
    for (int er = 0; er < 8; ++er) {
        float4 d0 = *(const float4*)(Pd + (size_t)dsts[er] * H + c0);
        float4 s0 = *(const float4*)(Ps + (size_t)srcs[er] * H + c0);
        acc[er][0] = d0.x + s0.x + bv.x;
        acc[er][1] = d0.y + s0.y + bv.y;
        acc[er][2] = d0.z + s0.z + bv.z;
        acc[er][3] = d0.w + s0.w + bv.w;
    }
}

__device__ __forceinline__ void load_acc_p(
    float acc[8][4], const float* __restrict__ Ps,
    const int* srcs, const float* __restrict__ b, int c0)
{
    float4 bv = *(const float4*)(b + c0);
#pragma unroll
    for (int er = 0; er < 8; ++er) {
        float4 s0 = *(const float4*)(Ps + (size_t)srcs[er] * H + c0);
        acc[er][0] = s0.x + bv.x;
        acc[er][1] = s0.y + bv.y;
        acc[er][2] = s0.z + bv.z;
        acc[er][3] = s0.w + bv.w;
    }
}

__device__ __forceinline__ void store_hidden_gelu(float acc[8][4], float* __restrict__ Hm,
                                                  int stride, int r0, int c0) {
#pragma unroll
    for (int er = 0; er < 8; ++er) {
        float4 v = make_float4(gelu_exact(acc[er][0]), gelu_exact(acc[er][1]),
                               gelu_exact(acc[er][2]), gelu_exact(acc[er][3]));
        *(float4*)(Hm + (r0 + er) * stride + c0) = v;
    }
}

// ---------------- K1: LN1 fused + node-level precompute (tf32 MMA) ----------------
__global__ __launch_bounds__(256, 2) void pre_kernel(
    const float* __restrict__ x,
    const float* __restrict__ ln1g, const float* __restrict__ ln1b,
    const float* __restrict__ Wg1, const float* __restrict__ Wa1,
    const float* __restrict__ Wm1, int N)
{
    extern __shared__ float sm[];
    float* At = sm;                 // [64][132]
    float* Wt = At + 64 * 132;      // 2 x [32][136]
    float* mu = Wt + 2 * 32 * LDW;  // [64]
    float* rs = mu + 64;            // [64]

    int tx = threadIdx.x;
    int n_base = blockIdx.x * 64;
    { // gather x tile
        int le = tx >> 2, q = tx & 3;
        int n = n_base + le;
        bool valid = n < N;
        const float4* xr = (const float4*)(x + (size_t)(valid ? n : 0) * H);
        float* ar = At + le * 132;
        float4 z = make_float4(0.f, 0.f, 0.f, 0.f);
#pragma unroll
        for (int jj = 0; jj < 8; ++jj) { int j = q + jj * 4; *(float4*)(ar + j * 4) = valid ? xr[j] : z; }
    }
    __syncthreads();

    { // LN1 stats: 4 threads per row
        int row = tx >> 2, q = tx & 3;
        const float* xr = At + row * 132 + q * 32;
        float s = 0.f, s2 = 0.f;
#pragma unroll 8
        for (int c = 0; c < 32; ++c) { float v = xr[c]; s += v; s2 = fmaf(v, v, s2); }
        s  += __shfl_xor_sync(0xffffffffu, s, 1);
        s  += __shfl_xor_sync(0xffffffffu, s, 2);
        s2 += __shfl_xor_sync(0xffffffffu, s2, 1);
        s2 += __shfl_xor_sync(0xffffffffu, s2, 2);
        if (q == 0) {
            float m = s * (1.0f / 128.0f);
            mu[row] = m;
            rs[row] = rsqrtf(fmaxf(s2 * (1.0f / 128.0f) - m * m, 0.0f) + 1e-5f);
        }
    }
    __syncthreads();

    { // normalize At in place + write g_h
#pragma unroll
        for (int i = 0; i < 8; ++i) {
            int f4 = tx + i * 256;
            int row = f4 >> 5;
            int c4 = (f4 & 31);
            float m = mu[row], r = rs[row];
            float4 v = *(const float4*)(At + row * 132 + c4 * 4);
            float4 g = ((const float4*)ln1g)[c4];
            float4 b = ((const float4*)ln1b)[c4];
            float4 nv = make_float4((v.x - m) * r * g.x + b.x, (v.y - m) * r * g.y + b.y,
                                    (v.z - m) * r * g.z + b.z, (v.w - m) * r * g.w + b.w);
            *(float4*)(At + row * 132 + c4 * 4) = nv;
            int n = n_base + row;
            if (n < N) ((float4*)(g_h + (size_t)n * H))[c4] = nv;
        }
    }

    const int wid = tx >> 5, lane = tx & 31;
    const int g = lane >> 2, t = lane & 3;
    const int m0 = (wid & 3) * 16;
    const int n0b = (wid >> 2) * 64;

    const float* Ws[5] = {Wg1, Wg1 + 128 * 128, Wa1, Wa1 + 128 * 128, Wm1};
    float* Os[5];
    Os[0] = g_Pgd; Os[1] = g_Pgs; Os[2] = g_Pad; Os[3] = g_Pas; Os[4] = g_Pms;

#pragma unroll 1
    for (int p = 0; p < 5; ++p) {
        float acc[8][4];
#pragma unroll
        for (int nt = 0; nt < 8; ++nt)
#pragma unroll
            for (int cj = 0; cj < 4; ++cj) acc[nt][cj] = 0.0f;
        gemm_mma_t<128, 132, 128>(At, Ws[p], 0, Wt, acc);
        int nA = n_base + m0 + g, nB = n_base + m0 + g + 8;
#pragma unroll
        for (int nt = 0; nt < 8; ++nt) {
            int cA = n0b + nt * 8 + 2 * t;
            if (nA < N) *(float2*)(Os[p] + (size_t)nA * H + cA) = make_float2(acc[nt][0], acc[nt][1]);
            if (nB < N) *(float2*)(Os[p] + (size_t)nB * H + cA) = make_float2(acc[nt][2], acc[nt][3]);
        }
    }
}

// ---------------- init: zero agg / denom / maxkey ----------------
__global__ __launch_bounds__(256) void init_kernel(int N)
{
    int i = blockIdx.x * 256 + threadIdx.x;
    if (i < N * H) g_agg[i] = 0.0f;
    if (i < N) { g_maxkey[i] = 0u; g_denom[i] = 0.0f; }
}

// ---------------- K2: per-edge MLPs (unchanged proven fp32 path) ----------------
__global__ __launch_bounds__(256, 2) void edge_kernel(
    const int* __restrict__ esrc, const int* __restrict__ edst,
    const float* __restrict__ emb,
    const float* __restrict__ Wm1, const float* __restrict__ bm1,
    const float* __restrict__ Wm2, const float* __restrict__ bm2,
    const float* __restrict__ Wa1, const float* __restrict__ ba1,
    const float* __restrict__ Wa2, const float* __restrict__ ba2,
    const float* __restrict__ Wg1, const float* __restrict__ bg1,
    const float* __restrict__ Wg2, const float* __restrict__ bg2,
    int E)
{
    extern __shared__ float sm[];
    float* Hm    = sm;                 // [64][132]
    float* Fe    = Hm + 64 * 132;      // [64][68]
    float* Wt    = Fe + 64 * 68;       // 2 x [32][128]
    float* gateS = Wt + 2 * 32 * 128;  // [64]
    int*   sidx  = (int*)(gateS + 64); // [64]
    int*   didx  = sidx + 64;          // [64]

    int tx = threadIdx.x;
    int e_base = blockIdx.x * 64;

    if (tx < 64) {
        int e = e_base + tx;
        sidx[tx] = (e < E) ? esrc[e] : 0;
        didx[tx] = (e < E) ? edst[e] : 0;
    }
    { // gather edge_emb
        int le = tx >> 2, q = tx & 3;
        int e = e_base + le;
        bool valid = e < E;
        const float4* em4 = (const float4*)(emb + (size_t)e * ED);
        float4 z = make_float4(0.f, 0.f, 0.f, 0.f);
        float* fr = Fe + le * 68;
#pragma unroll
        for (int jj = 0; jj < 4; ++jj) { int j = q + jj * 4; *(float4*)(fr + j * 4) = valid ? em4[j] : z; }
    }
    __syncthreads();

    int r0 = (tx >> 5) * 8;
    int c0 = (tx & 31) * 4;
    float acc[8][4];
    int srcs[8], dsts[8];
#pragma unroll
    for (int er = 0; er < 8; ++er) { srcs[er] = sidx[r0 + er]; dsts[er] = didx[r0 + er]; }

    // gate path
    load_acc_pp(acc, g_Pgd, g_Pgs, dsts, srcs, bg1, c0);
    gemm_acc_t<64, 68, 128>(Fe, Wg1 + (size_t)256 * 128, 0, Wt, acc);
    store_hidden_gelu(acc, Hm, 132, r0, c0);
    __syncthreads();
    {
        int row = tx >> 2, q = tx & 3;
        const float* hr = Hm + row * 132 + q * 32;
        const float* w  = Wg2 + q * 32;
        float s = 0.f;
#pragma unroll 8
        for (int c = 0; c < 32; ++c) s = fmaf(hr[c], w[c], s);
        s += __shfl_xor_sync(0xffffffffu, s, 1);
        s += __shfl_xor_sync(0xffffffffu, s, 2);
        if (q == 0) gateS[row] = 1.0f / (1.0f + expf(-(s + bg2[0])));
    }

    // attn path
    load_acc_pp(acc, g_Pad, g_Pas, dsts, srcs, ba1, c0);
    gemm_acc_t<64, 68, 128>(Fe, Wa1 + (size_t)256 * 128, 0, Wt, acc);
    store_hidden_gelu(acc, Hm, 132, r0, c0);
    __syncthreads();
    {
        int row = tx >> 2, q = tx & 3;
        const float* hr = Hm + row * 132 + q * 32;
        const float* w  = Wa2 + q * 32;
        float s = 0.f;
#pragma unroll 8
        for (int c = 0; c < 32; ++c) s = fmaf(hr[c], w[c], s);
        s += __shfl_xor_sync(0xffffffffu, s, 1);
        s += __shfl_xor_sync(0xffffffffu, s, 2);
        int e = e_base + row;
        if (q == 0 && e < E) g_score[e] = s + ba2[0];
    }

    // msg path
    load_acc_p(acc, g_Pms, srcs, bm1, c0);
    gemm_acc_t<64, 68, 128>(Fe, Wm1 + (size_t)128 * 128, 0, Wt, acc);
    store_hidden_gelu(acc, Hm, 132, r0, c0);
    init_acc_bias(acc, bm2 + c0);
    gemm_acc_t<128, 132, 128>(Hm, Wm2, 0, Wt, acc);
#pragma unroll
    for (int er = 0; er < 8; ++er) {
        int e = e_base + r0 + er;
        if (e < E) {
            float g = gateS[r0 + er];
            *(float4*)(g_msg + (size_t)e * H + c0) =
                make_float4(acc[er][0] * g, acc[er][1] * g, acc[er][2] * g, acc[er][3] * g);
        }
    }
}

// ---------------- K3: segment softmax ----------------
__global__ __launch_bounds__(256) void smax_kernel(const int* __restrict__ edst, int E)
{
    int e = blockIdx.x * 256 + threadIdx.x;
    if (e >= E) return;
    int i = __float_as_int(g_score[e]);
    unsigned key = (i >= 0) ? ((unsigned)i ^ 0x80000000u) : ~(unsigned)i;
    atomicMax(&g_maxkey[edst[e]], key);
}

__global__ __launch_bounds__(256) void exps_kernel(const int* __restrict__ edst, int E)
{
    int e = blockIdx.x * 256 + threadIdx.x;
    if (e >= E) return;
    int d = edst[e];
    unsigned k = g_maxkey[d];
    int bits = (k & 0x80000000u) ? (int)(k ^ 0x80000000u) : (int)~k;
    float m = __int_as_float(bits);
    float v = expf(g_score[e] - m);
    g_exp[e] = v;
    atomicAdd(&g_denom[d], v);
}

// ---------------- K4: edge_repr + scatter-add agg ----------------
__global__ __launch_bounds__(256) void scatter_kernel(
    const int* __restrict__ edst, float* __restrict__ erep, int E)
{
    int idx = blockIdx.x * 256 + threadIdx.x;
    int e = idx >> 5;
    if (e >= E) return;
    int l4 = idx & 31;
    int d = edst[e];
    float w = g_exp[e] / fmaxf(g_denom[d], 1e-12f);
    float4 m = ((const float4*)(g_msg + (size_t)e * H))[l4];
    float4 r = make_float4(m.x * w, m.y * w, m.z * w, m.w * w);
    ((float4*)(erep + (size_t)e * H))[l4] = r;
    float* ag = g_agg + (size_t)d * H + (size_t)l4 * 4;
    asm volatile("red.global.add.v4.f32 [%0], {%1, %2, %3, %4};"
                 :: "l"(ag), "f"(r.x), "f"(r.y), "f"(r.z), "f"(r.w)
                 : "memory");
}

// ---------------- K5: node update + LN2 + FFN (tf32 MMA, 2 blocks/SM) ------------
__global__ __launch_bounds__(256, 2) void node_kernel(
    const float* __restrict__ x,
    const float* __restrict__ Wself, const float* __restrict__ bself,
    const float* __restrict__ Wagg, const float* __restrict__ bagg,
    const float* __restrict__ g2, const float* __restrict__ b2,
    const float* __restrict__ Wf1, const float* __restrict__ bf1,
    const float* __restrict__ Wf2, const float* __restrict__ bf2,
    float* __restrict__ out, int N)
{
    extern __shared__ float sm[];
    float* At = sm;                  // [64][132] A operand
    float* Hc = At + 64 * 132;       // [64][132] out1 then FFN hidden chunk
    float* Wt = Hc + 64 * 132;       // 2 x [32][136]
    float* mu = Wt + 2 * 32 * LDW;   // [64]
    float* rs = mu + 64;             // [64]

    int tx = threadIdx.x;
    int n_base = blockIdx.x * 64;
    const int wid = tx >> 5, lane = tx & 31;
    const int g = lane >> 2, t = lane & 3;
    const int m0 = (wid & 3) * 16;
    const int n0b = (wid >> 2) * 64;
    const int rA = m0 + g, rB = m0 + g + 8;
    const int nA = n_base + rA, nB = n_base + rB;
    float acc[8][4];

    { // gather h -> At
        int le = tx >> 2, q = tx & 3;
        int n = n_base + le;
        bool valid = n < N;
        const float4* hr = (const float4*)(g_h + (size_t)(valid ? n : 0) * H);
        float* ar = At + le * 132;
        float4 z = make_float4(0.f, 0.f, 0.f, 0.f);
#pragma unroll
        for (int jj = 0; jj < 8; ++jj) { int j = q + jj * 4; *(float4*)(ar + j * 4) = valid ? hr[j] : z; }
    }

    { // acc = bself + bagg (mma layout)
#pragma unroll
        for (int nt = 0; nt < 8; ++nt) {
            int cA = n0b + nt * 8 + 2 * t;
            float2 a0 = *(const float2*)(bself + cA);
            float2 g0 = *(const float2*)(bagg + cA);
            acc[nt][0] = a0.x + g0.x; acc[nt][1] = a0.y + g0.y;
            acc[nt][2] = a0.x + g0.x; acc[nt][3] = a0.y + g0.y;
        }
    }
    gemm_mma_t<128, 132, 128>(At, Wself, 0, Wt, acc);

    { // overwrite At with agg (gemm's trailing sync makes this safe)
        int le = tx >> 2, q = tx & 3;
        int n = n_base + le;
        bool valid = n < N;
        const float4* gr = (const float4*)(g_agg + (size_t)(valid ? n : 0) * H);
        float* ar = At + le * 132;
        float4 z = make_float4(0.f, 0.f, 0.f, 0.f);
#pragma unroll
        for (int jj = 0; jj < 8; ++jj) { int j = q + jj * 4; *(float4*)(ar + j * 4) = valid ? gr[j] : z; }
    }
    gemm_mma_t<128, 132, 128>(At, Wagg, 0, Wt, acc);

    // out1 = x + update: write to g_h (park) and Hc (for LN2)
#pragma unroll
    for (int nt = 0; nt < 8; ++nt) {
        int cA = n0b + nt * 8 + 2 * t;
        float2 xA = make_float2(0.f, 0.f), xB = make_float2(0.f, 0.f);
        if (nA < N) xA = *(const float2*)(x + (size_t)nA * H + cA);
        if (nB < N) xB = *(const float2*)(x + (size_t)nB * H + cA);
        float2 oA = make_float2(acc[nt][0] + xA.x, acc[nt][1] + xA.y);
        float2 oB = make_float2(acc[nt][2] + xB.x, acc[nt][3] + xB.y);
        if (nA < N) *(float2*)(g_h + (size_t)nA * H + cA) = oA;
        if (nB < N) *(float2*)(g_h + (size_t)nB * H + cA) = oB;
        *(float2*)(Hc + rA * 132 + cA) = oA;
        *(float2*)(Hc + rB * 132 + cA) = oB;
    }
    __syncthreads();

    // LN2 stats: 4 threads per row from Hc
    {
        int row = tx >> 2, q = tx & 3;
        const float* orow = Hc + row * 132 + q * 32;
        float s = 0.f, s2 = 0.f;
#pragma unroll 8
        for (int c = 0; c < 32; ++c) { float v = orow[c]; s += v; s2 = fmaf(v, v, s2); }
        s  += __shfl_xor_sync(0xffffffffu, s, 1);
        s  += __shfl_xor_sync(0xffffffffu, s, 2);
        s2 += __shfl_xor_sync(0xffffffffu, s2, 1);
        s2 += __shfl_xor_sync(0xffffffffu, s2, 2);
        if (q == 0) {
            float m = s * (1.0f / 128.0f);
            mu[row] = m;
            rs[row] = rsqrtf(fmaxf(s2 * (1.0f / 128.0f) - m * m, 0.0f) + 1e-5f);
        }
    }
    __syncthreads();

    { // normalize Hc -> At
        int le = tx & 63, cb = tx >> 6;
        float m = mu[le], r = rs[le];
        const float* orow = Hc + le * 132;
        float* ar = At + le * 132;
#pragma unroll 4
        for (int c = cb * 32; c < cb * 32 + 32; ++c)
            ar[c] = (orow[c] - m) * r * g2[c] + b2[c];
    }
    // gemm prologue sync orders the At writes (and Hc reads finish before
    // Hc is overwritten after that gemm's syncs)

    // FFN chunked: gelu hidden chunk -> Hc (mma layout elementwise), then FFN2
    // partial into persistent accB.
    float accB[8][4];
#pragma unroll
    for (int nt = 0; nt < 8; ++nt) {
        int cA = n0b + nt * 8 + 2 * t;
        float2 bv = *(const float2*)(bf2 + cA);
        accB[nt][0] = bv.x; accB[nt][1] = bv.y;
        accB[nt][2] = bv.x; accB[nt][3] = bv.y;
    }
#pragma unroll 1
    for (int chunk = 0; chunk < 2; ++chunk) {
        int coff = chunk * 128;
#pragma unroll
        for (int nt = 0; nt < 8; ++nt) {
            int cA = n0b + nt * 8 + 2 * t;
            float2 bv = *(const float2*)(bf1 + coff + cA);
            acc[nt][0] = bv.x; acc[nt][1] = bv.y;
            acc[nt][2] = bv.x; acc[nt][3] = bv.y;
        }
        gemm_mma_t<128, 132, 256>(At, Wf1, coff, Wt, acc);
        // gelu -> Hc (chunk-local columns)
#pragma unroll
        for (int nt = 0; nt < 8; ++nt) {
            int cA = n0b + nt * 8 + 2 * t;
            *(float2*)(Hc + rA * 132 + cA) =
                make_float2(gelu_exact(acc[nt][0]), gelu_exact(acc[nt][1]));
            *(float2*)(Hc + rB * 132 + cA) =
                make_float2(gelu_exact(acc[nt][2]), gelu_exact(acc[nt][3]));
        }
        gemm_mma_t<128, 132, 128>(Hc, Wf2 + (size_t)coff * 128, 0, Wt, accB);
    }

    // final: out = out1(g_h) + accB
#pragma unroll
    for (int nt = 0; nt < 8; ++nt) {
        int cA = n0b + nt * 8 + 2 * t;
        if (nA < N) {
            float2 o = *(const float2*)(g_h + (size_t)nA * H + cA);
            *(float2*)(out + (size_t)nA * H + cA) =
                make_float2(o.x + accB[nt][0], o.y + accB[nt][1]);
        }
        if (nB < N) {
            float2 o = *(const float2*)(g_h + (size_t)nB * H + cA);
            *(float2*)(out + (size_t)nB * H + cA) =
                make_float2(o.x + accB[nt][2], o.y + accB[nt][3]);
        }
    }
}

// ---------------- launch ----------------
extern "C" void kernel_launch(void* const* d_in, const int* in_sizes, int n_in,
                              void* d_out, int out_size)
{
    const float* x     = (const float*)d_in[0];
    const int*   esrc  = (const int*)d_in[1];
    const int*   edst  = (const int*)d_in[2];
    const float* emb   = (const float*)d_in[3];
    const float* ln1g  = (const float*)d_in[4];
    const float* ln1b  = (const float*)d_in[5];
    const float* ln2g  = (const float*)d_in[6];
    const float* ln2b  = (const float*)d_in[7];
    const float* Wself = (const float*)d_in[8];
    const float* bself = (const float*)d_in[9];
    const float* Wm1   = (const float*)d_in[10];
    const float* bm1   = (const float*)d_in[11];
    const float* Wm2   = (const float*)d_in[12];
    const float* bm2   = (const float*)d_in[13];
    const float* Wa1   = (const float*)d_in[14];
    const float* ba1   = (const float*)d_in[15];
    const float* Wa2   = (const float*)d_in[16];
    const float* ba2   = (const float*)d_in[17];
    const float* Wg1   = (const float*)d_in[18];
    const float* bg1   = (const float*)d_in[19];
    const float* Wg2   = (const float*)d_in[20];
    const float* bg2   = (const float*)d_in[21];
    const float* Wagg  = (const float*)d_in[22];
    const float* bagg  = (const float*)d_in[23];
    const float* Wf1   = (const float*)d_in[24];
    const float* bf1   = (const float*)d_in[25];
    const float* Wf2   = (const float*)d_in[26];
    const float* bf2   = (const float*)d_in[27];

    int N = in_sizes[0] / H;
    int E = in_sizes[1];

    float* out_nodes = (float*)d_out;
    float* out_edges = out_nodes + (size_t)N * H;

    const int PRE_SMEM  = (64 * 132 + 2 * 32 * LDW + 128) * 4;                    // 69,632-ish
    const int EDGE_SMEM = (64 * 132 + 64 * 68 + 2 * 32 * 128 + 64 + 128) * 4;     // 84,736
    const int NODE_SMEM = (64 * 132 * 2 + 2 * 32 * LDW + 128) * 4;                // 103,424-ish
    cudaFuncSetAttribute(pre_kernel,  cudaFuncAttributeMaxDynamicSharedMemorySize, PRE_SMEM);
    cudaFuncSetAttribute(edge_kernel, cudaFuncAttributeMaxDynamicSharedMemorySize, EDGE_SMEM);
    cudaFuncSetAttribute(node_kernel, cudaFuncAttributeMaxDynamicSharedMemorySize, NODE_SMEM);

    pre_kernel<<<(N + 63) / 64, 256, PRE_SMEM>>>(x, ln1g, ln1b, Wg1, Wa1, Wm1, N);
    init_kernel<<<(N * H + 255) / 256, 256>>>(N);
    edge_kernel<<<(E + 63) / 64, 256, EDGE_SMEM>>>(
        esrc, edst, emb, Wm1, bm1, Wm2, bm2, Wa1, ba1, Wa2, ba2,
        Wg1, bg1, Wg2, bg2, E);
    smax_kernel<<<(E + 255) / 256, 256>>>(edst, E);
    exps_kernel<<<(E + 255) / 256, 256>>>(edst, E);
    scatter_kernel<<<((size_t)E * 32 + 255) / 256, 256>>>(edst, out_edges, E);
    node_kernel<<<(N + 63) / 64, 256, NODE_SMEM>>>(
        x, Wself, bself, Wagg, bagg, ln2g, ln2b, Wf1, bf1, Wf2, bf2,
        out_nodes, N);
}

// round 17
// speedup vs baseline: 1.8039x; 1.2434x over previous
#include <cuda_runtime.h>
#include <math.h>

#define H   128
#define ED  64
#define MAXN 100000
#define MAXE 500000

// ---------------- scratch (device globals; no allocations allowed) ----------------
__device__ float    g_h[(size_t)MAXN * H];      // LN1 output; later reused to park out1
__device__ float    g_msg[(size_t)MAXE * H];    // gated messages
__device__ float    g_score[MAXE];              // attention scores
__device__ float    g_exp[MAXE];                // exp(score - max)
__device__ unsigned g_maxkey[MAXN];             // ordered-uint segment max
__device__ float    g_denom[MAXN];              // segment sum of exp
__device__ float    g_agg[(size_t)MAXN * H];    // aggregated messages
// node-level precomputed first-layer partials (no bias)
__device__ float    g_Pgd[(size_t)MAXN * H];
__device__ float    g_Pgs[(size_t)MAXN * H];
__device__ float    g_Pad[(size_t)MAXN * H];
__device__ float    g_Pas[(size_t)MAXN * H];
__device__ float    g_Pms[(size_t)MAXN * H];
// tf32-rounded (round-to-nearest) weight copies
__device__ float    g_rWg1[320 * 128];
__device__ float    g_rWa1[320 * 128];
__device__ float    g_rWm1[192 * 128];
__device__ float    g_rWm2[128 * 128];
__device__ float    g_rWself[128 * 128];
__device__ float    g_rWagg[128 * 128];
__device__ float    g_rWf1[128 * 256];
__device__ float    g_rWf2[256 * 128];

// ---------------- helpers ----------------
__device__ __forceinline__ float gelu_exact(float v) {
    return 0.5f * v * (1.0f + erff(v * 0.70710678118654752440f));
}

__device__ __forceinline__ unsigned tf32r(float v) {
    unsigned r; asm("cvt.rna.tf32.f32 %0, %1;" : "=r"(r) : "f"(v)); return r;
}

__device__ __forceinline__ void cp16(float* dst, const float* src) {
    unsigned s = (unsigned)__cvta_generic_to_shared(dst);
    asm volatile("cp.async.cg.shared.global [%0], [%1], 16;" :: "r"(s), "l"(src) : "memory");
}
#define CP_COMMIT() asm volatile("cp.async.commit_group;" ::: "memory")
#define CP_WAIT0()  asm volatile("cp.async.wait_group 0;" ::: "memory")

// ================= tf32 MMA tiled GEMM =================
// C[64 rows][128 cols] += A[64][K] * W[K][128]; A in smem row-major (stride LDA).
// W (pre-rounded to tf32) streamed via cp.async, smem tile 32x128 @ stride 136.
// 8 warps: warp w -> m0 = (w&3)*16, n-half = (w>>2)*64; 8 n-tiles of m16n8k8.
// A fragments converted with cvt.rna (round-to-nearest tf32).
#define LDW 136

template<int K, int LDA, int LDWG>
__device__ __forceinline__ void gemm_mma_t(
    const float* __restrict__ As,
    const float* __restrict__ Wg, int woff,
    float* __restrict__ Wts, float acc[8][4])
{
    constexpr int NT = K / 32;
    const int tx   = threadIdx.x;
    const int wid  = tx >> 5;
    const int lane = tx & 31;
    const int g = lane >> 2, t = lane & 3;
    const int m0 = (wid & 3) * 16;
    const int n0b = (wid >> 2) * 64;
    const float* wptr = Wg + (size_t)wid * LDWG + woff + lane * 4;
    float* s0 = Wts + wid * LDW + lane * 4;

#pragma unroll
    for (int i = 0; i < 4; ++i)
        cp16(s0 + i * 8 * LDW, wptr + (size_t)(i * 8) * LDWG);
    CP_COMMIT();
    CP_WAIT0();
    __syncthreads();

    int cur = 0;
#pragma unroll 1
    for (int tt = 0; tt < NT; ++tt) {
        if (tt + 1 < NT) {
            float* sn = s0 + (cur ? 0 : 32 * LDW);
            const float* wn = wptr + (size_t)((tt + 1) * 32) * LDWG;
#pragma unroll
            for (int i = 0; i < 4; ++i)
                cp16(sn + i * 8 * LDW, wn + (size_t)(i * 8) * LDWG);
            CP_COMMIT();
        }
        const float* wb = Wts + (cur ? 32 * LDW : 0);
        const float* ab = As + tt * 32;
#pragma unroll
        for (int k8 = 0; k8 < 32; k8 += 8) {
            unsigned a0 = tf32r(ab[(m0 + g)     * LDA + k8 + t]);
            unsigned a1 = tf32r(ab[(m0 + g + 8) * LDA + k8 + t]);
            unsigned a2 = tf32r(ab[(m0 + g)     * LDA + k8 + t + 4]);
            unsigned a3 = tf32r(ab[(m0 + g + 8) * LDA + k8 + t + 4]);
#pragma unroll
            for (int nt = 0; nt < 8; ++nt) {
                int n8 = n0b + nt * 8;
                unsigned b0 = __float_as_uint(wb[(k8 + t)     * LDW + n8 + g]);
                unsigned b1 = __float_as_uint(wb[(k8 + t + 4) * LDW + n8 + g]);
                asm volatile(
                    "mma.sync.aligned.m16n8k8.row.col.f32.tf32.tf32.f32 "
                    "{%0,%1,%2,%3}, {%4,%5,%6,%7}, {%8,%9}, {%0,%1,%2,%3};"
                    : "+f"(acc[nt][0]), "+f"(acc[nt][1]),
                      "+f"(acc[nt][2]), "+f"(acc[nt][3])
                    : "r"(a0), "r"(a1), "r"(a2), "r"(a3), "r"(b0), "r"(b1));
            }
        }
        if (tt + 1 < NT) {
            CP_WAIT0();
            __syncthreads();
            cur ^= 1;
        }
    }
    __syncthreads();   // protect Wts and As for the caller's next phase
}

// ---------------- weight rounding kernel (run once, before everything) ----------
__global__ __launch_bounds__(256) void round_kernel(const float* __restrict__ W,
                                                    float* __restrict__ R, int n)
{
    int i = blockIdx.x * 256 + threadIdx.x;
    if (i < n) R[i] = __uint_as_float(tf32r(W[i]));
}

// ---------------- K1: LN1 fused + node-level precompute (tf32 MMA) ----------------
__global__ __launch_bounds__(256, 2) void pre_kernel(
    const float* __restrict__ x,
    const float* __restrict__ ln1g, const float* __restrict__ ln1b, int N)
{
    extern __shared__ float sm[];
    float* At = sm;                 // [64][132]
    float* Wt = At + 64 * 132;      // 2 x [32][136]
    float* mu = Wt + 2 * 32 * LDW;  // [64]
    float* rs = mu + 64;            // [64]

    int tx = threadIdx.x;
    int n_base = blockIdx.x * 64;
    { // gather x tile
        int le = tx >> 2, q = tx & 3;
        int n = n_base + le;
        bool valid = n < N;
        const float4* xr = (const float4*)(x + (size_t)(valid ? n : 0) * H);
        float* ar = At + le * 132;
        float4 z = make_float4(0.f, 0.f, 0.f, 0.f);
#pragma unroll
        for (int jj = 0; jj < 8; ++jj) { int j = q + jj * 4; *(float4*)(ar + j * 4) = valid ? xr[j] : z; }
    }
    __syncthreads();

    { // LN1 stats: 4 threads per row
        int row = tx >> 2, q = tx & 3;
        const float* xr = At + row * 132 + q * 32;
        float s = 0.f, s2 = 0.f;
#pragma unroll 8
        for (int c = 0; c < 32; ++c) { float v = xr[c]; s += v; s2 = fmaf(v, v, s2); }
        s  += __shfl_xor_sync(0xffffffffu, s, 1);
        s  += __shfl_xor_sync(0xffffffffu, s, 2);
        s2 += __shfl_xor_sync(0xffffffffu, s2, 1);
        s2 += __shfl_xor_sync(0xffffffffu, s2, 2);
        if (q == 0) {
            float m = s * (1.0f / 128.0f);
            mu[row] = m;
            rs[row] = rsqrtf(fmaxf(s2 * (1.0f / 128.0f) - m * m, 0.0f) + 1e-5f);
        }
    }
    __syncthreads();

    { // normalize At in place + write g_h
#pragma unroll
        for (int i = 0; i < 8; ++i) {
            int f4 = tx + i * 256;
            int row = f4 >> 5;
            int c4 = (f4 & 31);
            float m = mu[row], r = rs[row];
            float4 v = *(const float4*)(At + row * 132 + c4 * 4);
            float4 g = ((const float4*)ln1g)[c4];
            float4 b = ((const float4*)ln1b)[c4];
            float4 nv = make_float4((v.x - m) * r * g.x + b.x, (v.y - m) * r * g.y + b.y,
                                    (v.z - m) * r * g.z + b.z, (v.w - m) * r * g.w + b.w);
            *(float4*)(At + row * 132 + c4 * 4) = nv;
            int n = n_base + row;
            if (n < N) ((float4*)(g_h + (size_t)n * H))[c4] = nv;
        }
    }

    const int wid = tx >> 5, lane = tx & 31;
    const int g = lane >> 2, t = lane & 3;
    const int m0 = (wid & 3) * 16;
    const int n0b = (wid >> 2) * 64;

    const float* Ws[5] = {g_rWg1, g_rWg1 + 128 * 128, g_rWa1, g_rWa1 + 128 * 128, g_rWm1};
    float* Os[5];
    Os[0] = g_Pgd; Os[1] = g_Pgs; Os[2] = g_Pad; Os[3] = g_Pas; Os[4] = g_Pms;

#pragma unroll 1
    for (int p = 0; p < 5; ++p) {
        float acc[8][4];
#pragma unroll
        for (int nt = 0; nt < 8; ++nt)
#pragma unroll
            for (int cj = 0; cj < 4; ++cj) acc[nt][cj] = 0.0f;
        gemm_mma_t<128, 132, 128>(At, Ws[p], 0, Wt, acc);
        int nA = n_base + m0 + g, nB = n_base + m0 + g + 8;
#pragma unroll
        for (int nt = 0; nt < 8; ++nt) {
            int cA = n0b + nt * 8 + 2 * t;
            if (nA < N) *(float2*)(Os[p] + (size_t)nA * H + cA) = make_float2(acc[nt][0], acc[nt][1]);
            if (nB < N) *(float2*)(Os[p] + (size_t)nB * H + cA) = make_float2(acc[nt][2], acc[nt][3]);
        }
    }
}

// ---------------- init: zero agg / denom / maxkey ----------------
__global__ __launch_bounds__(256) void init_kernel(int N)
{
    int i = blockIdx.x * 256 + threadIdx.x;
    if (i < N * H) g_agg[i] = 0.0f;
    if (i < N) { g_maxkey[i] = 0u; g_denom[i] = 0.0f; }
}

// ---------------- K2: per-edge MLPs (tf32 MMA) ----------------
__global__ __launch_bounds__(256, 2) void edge_kernel(
    const int* __restrict__ esrc, const int* __restrict__ edst,
    const float* __restrict__ emb,
    const float* __restrict__ bm1, const float* __restrict__ bm2,
    const float* __restrict__ ba1,
    const float* __restrict__ Wa2, const float* __restrict__ ba2,
    const float* __restrict__ bg1,
    const float* __restrict__ Wg2, const float* __restrict__ bg2,
    int E)
{
    extern __shared__ float sm[];
    float* Hm    = sm;                 // [64][132] hidden buffer
    float* Fe    = Hm + 64 * 132;      // [64][68]  edge_emb tile
    float* Wt    = Fe + 64 * 68;       // 2 x [32][136]
    float* gateS = Wt + 2 * 32 * LDW;  // [64]
    int*   sidx  = (int*)(gateS + 64); // [64]
    int*   didx  = sidx + 64;          // [64]

    int tx = threadIdx.x;
    int e_base = blockIdx.x * 64;

    if (tx < 64) {
        int e = e_base + tx;
        sidx[tx] = (e < E) ? esrc[e] : 0;
        didx[tx] = (e < E) ? edst[e] : 0;
    }
    { // gather edge_emb
        int le = tx >> 2, q = tx & 3;
        int e = e_base + le;
        bool valid = e < E;
        const float4* em4 = (const float4*)(emb + (size_t)e * ED);
        float4 z = make_float4(0.f, 0.f, 0.f, 0.f);
        float* fr = Fe + le * 68;
#pragma unroll
        for (int jj = 0; jj < 4; ++jj) { int j = q + jj * 4; *(float4*)(fr + j * 4) = valid ? em4[j] : z; }
    }
    __syncthreads();

    const int wid = tx >> 5, lane = tx & 31;
    const int g = lane >> 2, t = lane & 3;
    const int m0 = (wid & 3) * 16;
    const int n0b = (wid >> 2) * 64;
    const int rA = m0 + g, rB = m0 + g + 8;
    const int eA = e_base + rA, eB = e_base + rB;
    const int dA = didx[rA], sA = sidx[rA];
    const int dB = didx[rB], sB = sidx[rB];
    float acc[8][4];

    // ---- gate path: gelu(Pgd[dst]+Pgs[src]+emb@Wg1_emb+bg1) @ Wg2 -> sigmoid
#pragma unroll
    for (int nt = 0; nt < 8; ++nt) {
        int cA = n0b + nt * 8 + 2 * t;
        float2 bv = *(const float2*)(bg1 + cA);
        float2 pdA = *(const float2*)(g_Pgd + (size_t)dA * H + cA);
        float2 psA = *(const float2*)(g_Pgs + (size_t)sA * H + cA);
        float2 pdB = *(const float2*)(g_Pgd + (size_t)dB * H + cA);
        float2 psB = *(const float2*)(g_Pgs + (size_t)sB * H + cA);
        acc[nt][0] = pdA.x + psA.x + bv.x; acc[nt][1] = pdA.y + psA.y + bv.y;
        acc[nt][2] = pdB.x + psB.x + bv.x; acc[nt][3] = pdB.y + psB.y + bv.y;
    }
    gemm_mma_t<64, 68, 128>(Fe, g_rWg1 + (size_t)256 * 128, 0, Wt, acc);
#pragma unroll
    for (int nt = 0; nt < 8; ++nt) {
        int cA = n0b + nt * 8 + 2 * t;
        *(float2*)(Hm + rA * 132 + cA) = make_float2(gelu_exact(acc[nt][0]), gelu_exact(acc[nt][1]));
        *(float2*)(Hm + rB * 132 + cA) = make_float2(gelu_exact(acc[nt][2]), gelu_exact(acc[nt][3]));
    }
    __syncthreads();
    { // 4 threads per row: 32 MACs + quad shfl reduce
        int row = tx >> 2, q = tx & 3;
        const float* hr = Hm + row * 132 + q * 32;
        const float* w  = Wg2 + q * 32;
        float s = 0.f;
#pragma unroll 8
        for (int c = 0; c < 32; ++c) s = fmaf(hr[c], w[c], s);
        s += __shfl_xor_sync(0xffffffffu, s, 1);
        s += __shfl_xor_sync(0xffffffffu, s, 2);
        if (q == 0) gateS[row] = 1.0f / (1.0f + expf(-(s + bg2[0])));
    }
    // next gemm's prologue sync separates dot reads of Hm from its overwrite

    // ---- attn path
#pragma unroll
    for (int nt = 0; nt < 8; ++nt) {
        int cA = n0b + nt * 8 + 2 * t;
        float2 bv = *(const float2*)(ba1 + cA);
        float2 pdA = *(const float2*)(g_Pad + (size_t)dA * H + cA);
        float2 psA = *(const float2*)(g_Pas + (size_t)sA * H + cA);
        float2 pdB = *(const float2*)(g_Pad + (size_t)dB * H + cA);
        float2 psB = *(const float2*)(g_Pas + (size_t)sB * H + cA);
        acc[nt][0] = pdA.x + psA.x + bv.x; acc[nt][1] = pdA.y + psA.y + bv.y;
        acc[nt][2] = pdB.x + psB.x + bv.x; acc[nt][3] = pdB.y + psB.y + bv.y;
    }
    gemm_mma_t<64, 68, 128>(Fe, g_rWa1 + (size_t)256 * 128, 0, Wt, acc);
#pragma unroll
    for (int nt = 0; nt < 8; ++nt) {
        int cA = n0b + nt * 8 + 2 * t;
        *(float2*)(Hm + rA * 132 + cA) = make_float2(gelu_exact(acc[nt][0]), gelu_exact(acc[nt][1]));
        *(float2*)(Hm + rB * 132 + cA) = make_float2(gelu_exact(acc[nt][2]), gelu_exact(acc[nt][3]));
    }
    __syncthreads();
    {
        int row = tx >> 2, q = tx & 3;
        const float* hr = Hm + row * 132 + q * 32;
        const float* w  = Wa2 + q * 32;
        float s = 0.f;
#pragma unroll 8
        for (int c = 0; c < 32; ++c) s = fmaf(hr[c], w[c], s);
        s += __shfl_xor_sync(0xffffffffu, s, 1);
        s += __shfl_xor_sync(0xffffffffu, s, 2);
        int e = e_base + row;
        if (q == 0 && e < E) g_score[e] = s + ba2[0];
    }

    // ---- msg path: gelu(Pms[src]+emb@Wm1_emb+bm1) @ Wm2 + bm2, then * gate
#pragma unroll
    for (int nt = 0; nt < 8; ++nt) {
        int cA = n0b + nt * 8 + 2 * t;
        float2 bv = *(const float2*)(bm1 + cA);
        float2 psA = *(const float2*)(g_Pms + (size_t)sA * H + cA);
        float2 psB = *(const float2*)(g_Pms + (size_t)sB * H + cA);
        acc[nt][0] = psA.x + bv.x; acc[nt][1] = psA.y + bv.y;
        acc[nt][2] = psB.x + bv.x; acc[nt][3] = psB.y + bv.y;
    }
    gemm_mma_t<64, 68, 128>(Fe, g_rWm1 + (size_t)128 * 128, 0, Wt, acc);
#pragma unroll
    for (int nt = 0; nt < 8; ++nt) {
        int cA = n0b + nt * 8 + 2 * t;
        *(float2*)(Hm + rA * 132 + cA) = make_float2(gelu_exact(acc[nt][0]), gelu_exact(acc[nt][1]));
        *(float2*)(Hm + rB * 132 + cA) = make_float2(gelu_exact(acc[nt][2]), gelu_exact(acc[nt][3]));
    }
#pragma unroll
    for (int nt = 0; nt < 8; ++nt) {
        int cA = n0b + nt * 8 + 2 * t;
        float2 bv = *(const float2*)(bm2 + cA);
        acc[nt][0] = bv.x; acc[nt][1] = bv.y;
        acc[nt][2] = bv.x; acc[nt][3] = bv.y;
    }
    gemm_mma_t<128, 132, 128>(Hm, g_rWm2, 0, Wt, acc);   // prologue sync covers Hm writes
    {
        float gA = gateS[rA], gB = gateS[rB];
#pragma unroll
        for (int nt = 0; nt < 8; ++nt) {
            int cA = n0b + nt * 8 + 2 * t;
            if (eA < E)
                *(float2*)(g_msg + (size_t)eA * H + cA) =
                    make_float2(acc[nt][0] * gA, acc[nt][1] * gA);
            if (eB < E)
                *(float2*)(g_msg + (size_t)eB * H + cA) =
                    make_float2(acc[nt][2] * gB, acc[nt][3] * gB);
        }
    }
}

// ---------------- K3: segment softmax ----------------
__global__ __launch_bounds__(256) void smax_kernel(const int* __restrict__ edst, int E)
{
    int e = blockIdx.x * 256 + threadIdx.x;
    if (e >= E) return;
    int i = __float_as_int(g_score[e]);
    unsigned key = (i >= 0) ? ((unsigned)i ^ 0x80000000u) : ~(unsigned)i;
    atomicMax(&g_maxkey[edst[e]], key);
}

__global__ __launch_bounds__(256) void exps_kernel(const int* __restrict__ edst, int E)
{
    int e = blockIdx.x * 256 + threadIdx.x;
    if (e >= E) return;
    int d = edst[e];
    unsigned k = g_maxkey[d];
    int bits = (k & 0x80000000u) ? (int)(k ^ 0x80000000u) : (int)~k;
    float m = __int_as_float(bits);
    float v = expf(g_score[e] - m);
    g_exp[e] = v;
    atomicAdd(&g_denom[d], v);
}

// ---------------- K4: edge_repr + scatter-add agg ----------------
__global__ __launch_bounds__(256) void scatter_kernel(
    const int* __restrict__ edst, float* __restrict__ erep, int E)
{
    int idx = blockIdx.x * 256 + threadIdx.x;
    int e = idx >> 5;
    if (e >= E) return;
    int l4 = idx & 31;
    int d = edst[e];
    float w = g_exp[e] / fmaxf(g_denom[d], 1e-12f);
    float4 m = ((const float4*)(g_msg + (size_t)e * H))[l4];
    float4 r = make_float4(m.x * w, m.y * w, m.z * w, m.w * w);
    ((float4*)(erep + (size_t)e * H))[l4] = r;
    float* ag = g_agg + (size_t)d * H + (size_t)l4 * 4;
    asm volatile("red.global.add.v4.f32 [%0], {%1, %2, %3, %4};"
                 :: "l"(ag), "f"(r.x), "f"(r.y), "f"(r.z), "f"(r.w)
                 : "memory");
}

// ---------------- K5: node update + LN2 + FFN (tf32 MMA, 2 blocks/SM) ------------
__global__ __launch_bounds__(256, 2) void node_kernel(
    const float* __restrict__ x,
    const float* __restrict__ bself, const float* __restrict__ bagg,
    const float* __restrict__ g2, const float* __restrict__ b2,
    const float* __restrict__ bf1, const float* __restrict__ bf2,
    float* __restrict__ out, int N)
{
    extern __shared__ float sm[];
    float* At = sm;                  // [64][132] A operand
    float* Hc = At + 64 * 132;       // [64][132] out1 then FFN hidden chunk
    float* Wt = Hc + 64 * 132;       // 2 x [32][136]
    float* mu = Wt + 2 * 32 * LDW;   // [64]
    float* rs = mu + 64;             // [64]

    int tx = threadIdx.x;
    int n_base = blockIdx.x * 64;
    const int wid = tx >> 5, lane = tx & 31;
    const int g = lane >> 2, t = lane & 3;
    const int m0 = (wid & 3) * 16;
    const int n0b = (wid >> 2) * 64;
    const int rA = m0 + g, rB = m0 + g + 8;
    const int nA = n_base + rA, nB = n_base + rB;
    float acc[8][4];

    { // gather h -> At
        int le = tx >> 2, q = tx & 3;
        int n = n_base + le;
        bool valid = n < N;
        const float4* hr = (const float4*)(g_h + (size_t)(valid ? n : 0) * H);
        float* ar = At + le * 132;
        float4 z = make_float4(0.f, 0.f, 0.f, 0.f);
#pragma unroll
        for (int jj = 0; jj < 8; ++jj) { int j = q + jj * 4; *(float4*)(ar + j * 4) = valid ? hr[j] : z; }
    }

    { // acc = bself + bagg (mma layout)
#pragma unroll
        for (int nt = 0; nt < 8; ++nt) {
            int cA = n0b + nt * 8 + 2 * t;
            float2 a0 = *(const float2*)(bself + cA);
            float2 g0 = *(const float2*)(bagg + cA);
            acc[nt][0] = a0.x + g0.x; acc[nt][1] = a0.y + g0.y;
            acc[nt][2] = a0.x + g0.x; acc[nt][3] = a0.y + g0.y;
        }
    }
    gemm_mma_t<128, 132, 128>(At, g_rWself, 0, Wt, acc);

    { // overwrite At with agg (gemm's trailing sync makes this safe)
        int le = tx >> 2, q = tx & 3;
        int n = n_base + le;
        bool valid = n < N;
        const float4* gr = (const float4*)(g_agg + (size_t)(valid ? n : 0) * H);
        float* ar = At + le * 132;
        float4 z = make_float4(0.f, 0.f, 0.f, 0.f);
#pragma unroll
        for (int jj = 0; jj < 8; ++jj) { int j = q + jj * 4; *(float4*)(ar + j * 4) = valid ? gr[j] : z; }
    }
    gemm_mma_t<128, 132, 128>(At, g_rWagg, 0, Wt, acc);

    // out1 = x + update: write to g_h (park) and Hc (for LN2)
#pragma unroll
    for (int nt = 0; nt < 8; ++nt) {
        int cA = n0b + nt * 8 + 2 * t;
        float2 xA = make_float2(0.f, 0.f), xB = make_float2(0.f, 0.f);
        if (nA < N) xA = *(const float2*)(x + (size_t)nA * H + cA);
        if (nB < N) xB = *(const float2*)(x + (size_t)nB * H + cA);
        float2 oA = make_float2(acc[nt][0] + xA.x, acc[nt][1] + xA.y);
        float2 oB = make_float2(acc[nt][2] + xB.x, acc[nt][3] + xB.y);
        if (nA < N) *(float2*)(g_h + (size_t)nA * H + cA) = oA;
        if (nB < N) *(float2*)(g_h + (size_t)nB * H + cA) = oB;
        *(float2*)(Hc + rA * 132 + cA) = oA;
        *(float2*)(Hc + rB * 132 + cA) = oB;
    }
    __syncthreads();

    // LN2 stats: 4 threads per row from Hc
    {
        int row = tx >> 2, q = tx & 3;
        const float* orow = Hc + row * 132 + q * 32;
        float s = 0.f, s2 = 0.f;
#pragma unroll 8
        for (int c = 0; c < 32; ++c) { float v = orow[c]; s += v; s2 = fmaf(v, v, s2); }
        s  += __shfl_xor_sync(0xffffffffu, s, 1);
        s  += __shfl_xor_sync(0xffffffffu, s, 2);
        s2 += __shfl_xor_sync(0xffffffffu, s2, 1);
        s2 += __shfl_xor_sync(0xffffffffu, s2, 2);
        if (q == 0) {
            float m = s * (1.0f / 128.0f);
            mu[row] = m;
            rs[row] = rsqrtf(fmaxf(s2 * (1.0f / 128.0f) - m * m, 0.0f) + 1e-5f);
        }
    }
    __syncthreads();

    { // normalize Hc -> At
        int le = tx & 63, cb = tx >> 6;
        float m = mu[le], r = rs[le];
        const float* orow = Hc + le * 132;
        float* ar = At + le * 132;
#pragma unroll 4
        for (int c = cb * 32; c < cb * 32 + 32; ++c)
            ar[c] = (orow[c] - m) * r * g2[c] + b2[c];
    }
    // gemm prologue sync orders the At writes

    // FFN chunked: gelu hidden chunk -> Hc (mma layout), FFN2 partial into accB.
    float accB[8][4];
#pragma unroll
    for (int nt = 0; nt < 8; ++nt) {
        int cA = n0b + nt * 8 + 2 * t;
        float2 bv = *(const float2*)(bf2 + cA);
        accB[nt][0] = bv.x; accB[nt][1] = bv.y;
        accB[nt][2] = bv.x; accB[nt][3] = bv.y;
    }
#pragma unroll 1
    for (int chunk = 0; chunk < 2; ++chunk) {
        int coff = chunk * 128;
#pragma unroll
        for (int nt = 0; nt < 8; ++nt) {
            int cA = n0b + nt * 8 + 2 * t;
            float2 bv = *(const float2*)(bf1 + coff + cA);
            acc[nt][0] = bv.x; acc[nt][1] = bv.y;
            acc[nt][2] = bv.x; acc[nt][3] = bv.y;
        }
        gemm_mma_t<128, 132, 256>(At, g_rWf1, coff, Wt, acc);
#pragma unroll
        for (int nt = 0; nt < 8; ++nt) {
            int cA = n0b + nt * 8 + 2 * t;
            *(float2*)(Hc + rA * 132 + cA) =
                make_float2(gelu_exact(acc[nt][0]), gelu_exact(acc[nt][1]));
            *(float2*)(Hc + rB * 132 + cA) =
                make_float2(gelu_exact(acc[nt][2]), gelu_exact(acc[nt][3]));
        }
        gemm_mma_t<128, 132, 128>(Hc, g_rWf2 + (size_t)coff * 128, 0, Wt, accB);
    }

    // final: out = out1(g_h) + accB
#pragma unroll
    for (int nt = 0; nt < 8; ++nt) {
        int cA = n0b + nt * 8 + 2 * t;
        if (nA < N) {
            float2 o = *(const float2*)(g_h + (size_t)nA * H + cA);
            *(float2*)(out + (size_t)nA * H + cA) =
                make_float2(o.x + accB[nt][0], o.y + accB[nt][1]);
        }
        if (nB < N) {
            float2 o = *(const float2*)(g_h + (size_t)nB * H + cA);
            *(float2*)(out + (size_t)nB * H + cA) =
                make_float2(o.x + accB[nt][2], o.y + accB[nt][3]);
        }
    }
}

// ---------------- launch ----------------
extern "C" void kernel_launch(void* const* d_in, const int* in_sizes, int n_in,
                              void* d_out, int out_size)
{
    const float* x     = (const float*)d_in[0];
    const int*   esrc  = (const int*)d_in[1];
    const int*   edst  = (const int*)d_in[2];
    const float* emb   = (const float*)d_in[3];
    const float* ln1g  = (const float*)d_in[4];
    const float* ln1b  = (const float*)d_in[5];
    const float* ln2g  = (const float*)d_in[6];
    const float* ln2b  = (const float*)d_in[7];
    const float* Wself = (const float*)d_in[8];
    const float* bself = (const float*)d_in[9];
    const float* Wm1   = (const float*)d_in[10];
    const float* bm1   = (const float*)d_in[11];
    const float* Wm2   = (const float*)d_in[12];
    const float* bm2   = (const float*)d_in[13];
    const float* Wa1   = (const float*)d_in[14];
    const float* ba1   = (const float*)d_in[15];
    const float* Wa2   = (const float*)d_in[16];
    const float* ba2   = (const float*)d_in[17];
    const float* Wg1   = (const float*)d_in[18];
    const float* bg1   = (const float*)d_in[19];
    const float* Wg2   = (const float*)d_in[20];
    const float* bg2   = (const float*)d_in[21];
    const float* Wagg  = (const float*)d_in[22];
    const float* bagg  = (const float*)d_in[23];
    const float* Wf1   = (const float*)d_in[24];
    const float* bf1   = (const float*)d_in[25];
    const float* Wf2   = (const float*)d_in[26];
    const float* bf2   = (const float*)d_in[27];

    int N = in_sizes[0] / H;
    int E = in_sizes[1];

    float* out_nodes = (float*)d_out;
    float* out_edges = out_nodes + (size_t)N * H;

    const int PRE_SMEM  = (64 * 132 + 2 * 32 * LDW + 128) * 4;
    const int EDGE_SMEM = (64 * 132 + 64 * 68 + 2 * 32 * LDW + 64 + 128) * 4;
    const int NODE_SMEM = (64 * 132 * 2 + 2 * 32 * LDW + 128) * 4;
    cudaFuncSetAttribute(pre_kernel,  cudaFuncAttributeMaxDynamicSharedMemorySize, PRE_SMEM);
    cudaFuncSetAttribute(edge_kernel, cudaFuncAttributeMaxDynamicSharedMemorySize, EDGE_SMEM);
    cudaFuncSetAttribute(node_kernel, cudaFuncAttributeMaxDynamicSharedMemorySize, NODE_SMEM);

    // tf32-round all weight matrices (round-to-nearest) into device copies
    float* rp;
#define ROUND(W, SYM, CNT) \
    cudaGetSymbolAddress((void**)&rp, SYM); \
    round_kernel<<<((CNT) + 255) / 256, 256>>>(W, rp, CNT);
    ROUND(Wg1,   g_rWg1,   320 * 128)
    ROUND(Wa1,   g_rWa1,   320 * 128)
    ROUND(Wm1,   g_rWm1,   192 * 128)
    ROUND(Wm2,   g_rWm2,   128 * 128)
    ROUND(Wself, g_rWself, 128 * 128)
    ROUND(Wagg,  g_rWagg,  128 * 128)
    ROUND(Wf1,   g_rWf1,   128 * 256)
    ROUND(Wf2,   g_rWf2,   256 * 128)
#undef ROUND

    pre_kernel<<<(N + 63) / 64, 256, PRE_SMEM>>>(x, ln1g, ln1b, N);
    init_kernel<<<(N * H + 255) / 256, 256>>>(N);
    edge_kernel<<<(E + 63) / 64, 256, EDGE_SMEM>>>(
        esrc, edst, emb, bm1, bm2, ba1, Wa2, ba2, bg1, Wg2, bg2, E);
    smax_kernel<<<(E + 255) / 256, 256>>>(edst, E);
    exps_kernel<<<(E + 255) / 256, 256>>>(edst, E);
    scatter_kernel<<<((size_t)E * 32 + 255) / 256, 256>>>(edst, out_edges, E);
    node_kernel<<<(N + 63) / 64, 256, NODE_SMEM>>>(
        x, bself, bagg, ln2g, ln2b, bf1, bf2, out_nodes, N);
}